// round 1
// baseline (speedup 1.0000x reference)
#include <cuda_runtime.h>

// Problem constants (fixed by the dataset)
#define NN 50000
#define EE 800000
#define HH 64
#define D0 128
#define DE 32
#define NEG 0.2f

// ---------------- scratch (static device globals; no allocation) ----------------
__device__ float g_h   [NN * HH];   // current layer transformed features
__device__ float g_x1  [NN * HH];   // layer-1 output
__device__ float g_x2  [NN * HH];   // layer-2 output
__device__ float g_agg [NN * HH];   // softmax-weighted aggregation accumulator
__device__ float g_u   [NN * HH];   // classifier: x2 @ Wc1[0:64]
__device__ float g_v   [NN * HH];   // classifier: x2 @ Wc1[64:128]
__device__ float g_ssrc[NN], g_sdst[NN];
__device__ float g_m[NN], g_lself[NN], g_denom[NN];
__device__ float g_sumt1[NN], g_sumt2[NN], g_deg[NN];
__device__ float g_t1[EE], g_t2[EE];
__device__ float g_wv1[DE], g_wv2[DE];

__device__ __forceinline__ float lrelu(float z) { return z >= 0.f ? z : NEG * z; }

__device__ __forceinline__ void atomicMaxFloat(float* addr, float val) {
    int* ia = (int*)addr;
    int old = *ia;
    while (__int_as_float(old) < val) {
        int assumed = old;
        old = atomicCAS(ia, assumed, __float_as_int(val));
        if (old == assumed) break;
    }
}

// ---------------- tiny prep: wv = We @ a_edge for both layers ----------------
__global__ void k_prep(const float* __restrict__ We1, const float* __restrict__ ae1,
                       const float* __restrict__ We2, const float* __restrict__ ae2) {
    int k = threadIdx.x;   // 32 threads
    float s1 = 0.f, s2 = 0.f;
    #pragma unroll 8
    for (int j = 0; j < HH; j++) {
        s1 = fmaf(We1[k * HH + j], ae1[j], s1);
        s2 = fmaf(We2[k * HH + j], ae2[j], s2);
    }
    g_wv1[k] = s1;
    g_wv2[k] = s2;
}

__global__ void k_zero_node() {
    int i = blockIdx.x * blockDim.x + threadIdx.x;
    if (i < NN) { g_deg[i] = 0.f; g_sumt1[i] = 0.f; g_sumt2[i] = 0.f; }
}

// t_e for both layers + degree + per-dst sums (for mean self-loop attr)
__global__ void __launch_bounds__(256) k_edge_t(const float* __restrict__ ea,
                                                const int* __restrict__ dst) {
    int e = blockIdx.x * blockDim.x + threadIdx.x;   // grid sized exactly EE/256
    const float4* p = (const float4*)(ea + (size_t)e * DE);
    float t1 = 0.f, t2 = 0.f;
    #pragma unroll
    for (int q = 0; q < 8; q++) {
        float4 v = p[q];
        t1 = fmaf(v.x, g_wv1[4*q+0], t1); t1 = fmaf(v.y, g_wv1[4*q+1], t1);
        t1 = fmaf(v.z, g_wv1[4*q+2], t1); t1 = fmaf(v.w, g_wv1[4*q+3], t1);
        t2 = fmaf(v.x, g_wv2[4*q+0], t2); t2 = fmaf(v.y, g_wv2[4*q+1], t2);
        t2 = fmaf(v.z, g_wv2[4*q+2], t2); t2 = fmaf(v.w, g_wv2[4*q+3], t2);
    }
    g_t1[e] = t1;
    g_t2[e] = t2;
    int d = dst[e];
    atomicAdd(&g_deg[d], 1.0f);
    atomicAdd(&g_sumt1[d], t1);
    atomicAdd(&g_sumt2[d], t2);
}

// ---------------- node GEMM fused with attention scalar projections ----------------
// h = xin @ W ; s_src = h . a_src ; s_dst = h . a_dst
// 256 threads = 4 rows x 64 cols. Grid = NN/4 (NN divisible by 4).
template <int DIN, int USE_X1>
__global__ void __launch_bounds__(256) k_gemm_hs(const float* __restrict__ xin_param,
                                                 const float* __restrict__ W,
                                                 const float* __restrict__ av_src,
                                                 const float* __restrict__ av_dst) {
    __shared__ float Ws[DIN * HH];
    __shared__ float sred[8][2];
    int tid = threadIdx.x;
    for (int i = tid; i < DIN * HH; i += 256) Ws[i] = W[i];
    __syncthreads();

    const float* xin = USE_X1 ? g_x1 : xin_param;
    int col = tid & 63, r = tid >> 6;
    int row = blockIdx.x * 4 + r;
    const float* xr = xin + (size_t)row * DIN;
    float acc = 0.f;
    #pragma unroll 16
    for (int k = 0; k < DIN; k++) acc = fmaf(xr[k], Ws[k * HH + col], acc);
    g_h[(size_t)row * HH + col] = acc;

    float ps = acc * av_src[col];
    float pd = acc * av_dst[col];
    #pragma unroll
    for (int o = 16; o > 0; o >>= 1) {
        ps += __shfl_down_sync(0xffffffffu, ps, o);
        pd += __shfl_down_sync(0xffffffffu, pd, o);
    }
    int warp = tid >> 5;
    if ((tid & 31) == 0) { sred[warp][0] = ps; sred[warp][1] = pd; }
    __syncthreads();
    if (col == 0) {
        g_ssrc[row] = sred[2*r][0] + sred[2*r+1][0];
        g_sdst[row] = sred[2*r][1] + sred[2*r+1][1];
    }
}

// self-loop logit; seed running max with it (every node has a self loop)
__global__ void k_node_init(int layer) {
    int n = blockIdx.x * blockDim.x + threadIdx.x;
    if (n >= NN) return;
    const float* sumt = layer ? g_sumt2 : g_sumt1;
    float tl = sumt[n] / fmaxf(g_deg[n], 1.0f);
    float l  = lrelu(g_ssrc[n] + g_sdst[n] + tl);
    g_lself[n] = l;
    g_m[n]     = l;
}

__global__ void __launch_bounds__(256) k_edge_max(const int* __restrict__ src,
                                                  const int* __restrict__ dst, int layer) {
    int e = blockIdx.x * blockDim.x + threadIdx.x;
    const float* t = layer ? g_t2 : g_t1;
    int d = dst[e];
    float l = lrelu(g_ssrc[src[e]] + g_sdst[d] + t[e]);
    atomicMaxFloat(&g_m[d], l);
}

__global__ void k_node_denom() {
    int n = blockIdx.x * blockDim.x + threadIdx.x;
    if (n >= NN) return;
    g_denom[n] = __expf(g_lself[n] - g_m[n]);   // self-loop term
}

__global__ void k_zero_agg() {
    int i = blockIdx.x * blockDim.x + threadIdx.x;   // grid = NN*HH/256 exactly
    g_agg[i] = 0.f;
}

__global__ void __launch_bounds__(256) k_edge_denom(const int* __restrict__ src,
                                                    const int* __restrict__ dst, int layer) {
    int e = blockIdx.x * blockDim.x + threadIdx.x;
    const float* t = layer ? g_t2 : g_t1;
    int d = dst[e];
    float l = lrelu(g_ssrc[src[e]] + g_sdst[d] + t[e]);
    atomicAdd(&g_denom[d], __expf(l - g_m[d]));
}

// weighted aggregation: 4 edges per block, 64 threads per edge
__global__ void __launch_bounds__(256) k_edge_agg(const int* __restrict__ src,
                                                  const int* __restrict__ dst, int layer) {
    int tid = threadIdx.x;
    int e = blockIdx.x * 4 + (tid >> 6);
    int c = tid & 63;
    const float* t = layer ? g_t2 : g_t1;
    int s = src[e], d = dst[e];
    float l = lrelu(g_ssrc[s] + g_sdst[d] + t[e]);
    float w = __expf(l - g_m[d]) / g_denom[d];
    atomicAdd(&g_agg[(size_t)d * HH + c], w * g_h[(size_t)s * HH + c]);
}

// out = relu(agg + alpha_self * h + b)
__global__ void __launch_bounds__(256) k_node_fin(const float* __restrict__ b, int layer) {
    int idx = blockIdx.x * blockDim.x + threadIdx.x;   // grid = NN*HH/256 exactly
    int n = idx >> 6, c = idx & 63;
    float alpha = __expf(g_lself[n] - g_m[n]) / g_denom[n];
    float v = g_agg[idx] + alpha * g_h[idx] + b[c];
    float* xout = layer ? g_x2 : g_x1;
    xout[idx] = fmaxf(v, 0.f);
}

// ---------------- classifier ----------------
// u = x2 @ Wc1[0:64], v = x2 @ Wc1[64:128]
__global__ void __launch_bounds__(256) k_gemm_uv(const float* __restrict__ Wc1) {
    __shared__ float Ws[2 * HH * HH];   // 32 KB: first 128 rows of Wc1
    int tid = threadIdx.x;
    for (int i = tid; i < 2 * HH * HH; i += 256) Ws[i] = Wc1[i];
    __syncthreads();
    int col = tid & 63, r = tid >> 6;
    int row = blockIdx.x * 4 + r;
    const float* xr = g_x2 + (size_t)row * HH;
    float au = 0.f, av = 0.f;
    #pragma unroll 16
    for (int k = 0; k < HH; k++) {
        float xv = xr[k];
        au = fmaf(xv, Ws[k * HH + col], au);
        av = fmaf(xv, Ws[(HH + k) * HH + col], av);
    }
    g_u[(size_t)row * HH + col] = au;
    g_v[(size_t)row * HH + col] = av;
}

// fused per-edge: relu(u[row]+v[col]+ea@Wc1[128:160]+bc1) @ Wc2 + bc2
__global__ void __launch_bounds__(256) k_classify(const int* __restrict__ src,
                                                  const int* __restrict__ dst,
                                                  const float* __restrict__ ea,
                                                  const float* __restrict__ Wc1,
                                                  const float* __restrict__ bc1,
                                                  const float* __restrict__ Wc2,
                                                  const float* __restrict__ bc2,
                                                  float* __restrict__ out) {
    __shared__ float Wb[DE * HH];   // 8 KB: rows 128..159 of Wc1
    __shared__ float sred[8];
    int tid = threadIdx.x;
    for (int i = tid; i < DE * HH; i += 256) Wb[i] = Wc1[2 * HH * HH + i];
    __syncthreads();

    int c = tid & 63, g = tid >> 6;
    int e = blockIdx.x * 4 + g;       // grid = EE/4 exactly
    int s = src[e], d = dst[e];
    float acc = g_u[(size_t)s * HH + c] + g_v[(size_t)d * HH + c] + bc1[c];
    const float* eap = ea + (size_t)e * DE;
    #pragma unroll
    for (int k = 0; k < DE; k++) acc = fmaf(eap[k], Wb[k * HH + c], acc);
    acc = fmaxf(acc, 0.f) * Wc2[c];
    #pragma unroll
    for (int o = 16; o > 0; o >>= 1) acc += __shfl_down_sync(0xffffffffu, acc, o);
    if ((tid & 31) == 0) sred[tid >> 5] = acc;
    __syncthreads();
    if (c == 0) out[e] = sred[2 * g] + sred[2 * g + 1] + bc2[0];
}

// ---------------- host launcher ----------------
extern "C" void kernel_launch(void* const* d_in, const int* in_sizes, int n_in,
                              void* d_out, int out_size) {
    const float* x    = (const float*)d_in[0];
    const int*   ei   = (const int*)  d_in[1];
    const float* ea   = (const float*)d_in[2];
    const float* W1   = (const float*)d_in[3];
    const float* We1  = (const float*)d_in[4];
    const float* as1  = (const float*)d_in[5];
    const float* ad1  = (const float*)d_in[6];
    const float* ae1  = (const float*)d_in[7];
    const float* b1   = (const float*)d_in[8];
    const float* W2   = (const float*)d_in[9];
    const float* We2  = (const float*)d_in[10];
    const float* as2  = (const float*)d_in[11];
    const float* ad2  = (const float*)d_in[12];
    const float* ae2  = (const float*)d_in[13];
    const float* b2   = (const float*)d_in[14];
    const float* Wc1  = (const float*)d_in[15];
    const float* bc1  = (const float*)d_in[16];
    const float* Wc2  = (const float*)d_in[17];
    const float* bc2  = (const float*)d_in[18];
    float*       out  = (float*)d_out;

    const int* src = ei;        // edge_index[0] = row
    const int* dst = ei + EE;   // edge_index[1] = col

    const int NB_N   = (NN + 255) / 256;   // node-count grid (guarded)
    const int NB_E   = EE / 256;           // 3125 (exact)
    const int NB_G   = NN / 4;             // 12500 (exact)
    const int NB_NH  = NN * HH / 256;      // 12500 (exact)
    const int NB_E4  = EE / 4;             // 200000 (exact)

    k_prep<<<1, 32>>>(We1, ae1, We2, ae2);
    k_zero_node<<<NB_N, 256>>>();
    k_edge_t<<<NB_E, 256>>>(ea, dst);

    // ---- GAT layer 1 ----
    k_gemm_hs<D0, 0><<<NB_G, 256>>>(x, W1, as1, ad1);
    k_node_init<<<NB_N, 256>>>(0);
    k_edge_max<<<NB_E, 256>>>(src, dst, 0);
    k_node_denom<<<NB_N, 256>>>();
    k_zero_agg<<<NB_NH, 256>>>();
    k_edge_denom<<<NB_E, 256>>>(src, dst, 0);
    k_edge_agg<<<NB_E4, 256>>>(src, dst, 0);
    k_node_fin<<<NB_NH, 256>>>(b1, 0);

    // ---- GAT layer 2 ----
    k_gemm_hs<HH, 1><<<NB_G, 256>>>(nullptr, W2, as2, ad2);
    k_node_init<<<NB_N, 256>>>(1);
    k_edge_max<<<NB_E, 256>>>(src, dst, 1);
    k_node_denom<<<NB_N, 256>>>();
    k_zero_agg<<<NB_NH, 256>>>();
    k_edge_denom<<<NB_E, 256>>>(src, dst, 1);
    k_edge_agg<<<NB_E4, 256>>>(src, dst, 1);
    k_node_fin<<<NB_NH, 256>>>(b2, 1);

    // ---- edge classifier ----
    k_gemm_uv<<<NB_G, 256>>>(Wc1);
    k_classify<<<NB_E4, 256>>>(src, dst, ea, Wc1, bc1, Wc2, bc2, out);
}

// round 2
// speedup vs baseline: 1.8357x; 1.8357x over previous
#include <cuda_runtime.h>

#define NN 50000
#define EE 800000
#define HH 64
#define D0 128
#define DE 32
#define NEG 0.2f

// ---------------- scratch (static device globals; no allocation) ----------------
__device__ float g_h  [NN * HH];
__device__ float g_x1 [NN * HH];
__device__ float g_x2 [NN * HH];
__device__ float g_u  [NN * HH];
__device__ float g_v  [NN * HH];
__device__ float g_ssrc[NN], g_sdst[NN];
__device__ int   g_degi[NN];
__device__ int   g_rowptr[NN + 1];
__device__ int   g_cnt[NN];
__device__ int   g_cs [EE];          // src ids, CSR (by dst) order
__device__ float g_ct1[EE], g_ct2[EE]; // t_e per layer, CSR order
__device__ float g_t1[EE], g_t2[EE];   // t_e per layer, original order (scatter staging)
__device__ float g_scr[EE];            // logits / softmax weights, CSR order
__device__ float g_wv1[DE], g_wv2[DE];

__device__ __forceinline__ float lrelu(float z) { return z >= 0.f ? z : NEG * z; }

// ---------------- wv = We @ a_edge ----------------
__global__ void k_prep(const float* __restrict__ We1, const float* __restrict__ ae1,
                       const float* __restrict__ We2, const float* __restrict__ ae2) {
    int k = threadIdx.x;   // 32 threads
    float s1 = 0.f, s2 = 0.f;
    #pragma unroll 8
    for (int j = 0; j < HH; j++) {
        s1 = fmaf(We1[k * HH + j], ae1[j], s1);
        s2 = fmaf(We2[k * HH + j], ae2[j], s2);
    }
    g_wv1[k] = s1;
    g_wv2[k] = s2;
}

__global__ void k_zero() {
    int i = blockIdx.x * blockDim.x + threadIdx.x;
    if (i < NN) { g_degi[i] = 0; g_cnt[i] = 0; }
}

// t_e for both layers + degree histogram
__global__ void __launch_bounds__(256) k_edge_t(const float* __restrict__ ea,
                                                const int* __restrict__ dst) {
    __shared__ float wv1s[DE], wv2s[DE];
    int tid = threadIdx.x;
    if (tid < DE) { wv1s[tid] = g_wv1[tid]; wv2s[tid] = g_wv2[tid]; }
    __syncthreads();
    int e = blockIdx.x * 256 + tid;           // grid exactly EE/256
    const float4* p = (const float4*)(ea + (size_t)e * DE);
    float t1 = 0.f, t2 = 0.f;
    #pragma unroll
    for (int q = 0; q < 8; q++) {
        float4 v = p[q];
        t1 = fmaf(v.x, wv1s[4*q+0], t1); t1 = fmaf(v.y, wv1s[4*q+1], t1);
        t1 = fmaf(v.z, wv1s[4*q+2], t1); t1 = fmaf(v.w, wv1s[4*q+3], t1);
        t2 = fmaf(v.x, wv2s[4*q+0], t2); t2 = fmaf(v.y, wv2s[4*q+1], t2);
        t2 = fmaf(v.z, wv2s[4*q+2], t2); t2 = fmaf(v.w, wv2s[4*q+3], t2);
    }
    g_t1[e] = t1;
    g_t2[e] = t2;
    atomicAdd(&g_degi[dst[e]], 1);
}

// single-block exclusive scan of degi -> rowptr
__global__ void __launch_bounds__(1024) k_scan() {
    __shared__ int ws[32];
    const int CH = 49;                 // 1024*49 = 50176 >= NN
    int t = threadIdx.x, lane = t & 31, w = t >> 5;
    int s0 = t * CH;
    int sum = 0;
    for (int i = 0; i < CH; i++) { int idx = s0 + i; if (idx < NN) sum += g_degi[idx]; }
    int v = sum;
    #pragma unroll
    for (int o = 1; o < 32; o <<= 1) { int x = __shfl_up_sync(0xffffffffu, v, o); if (lane >= o) v += x; }
    if (lane == 31) ws[w] = v;
    __syncthreads();
    if (w == 0) {
        int y = ws[lane];
        #pragma unroll
        for (int o = 1; o < 32; o <<= 1) { int x = __shfl_up_sync(0xffffffffu, y, o); if (lane >= o) y += x; }
        ws[lane] = y;
    }
    __syncthreads();
    int off = v - sum + (w > 0 ? ws[w - 1] : 0);
    for (int i = 0; i < CH; i++) {
        int idx = s0 + i;
        if (idx < NN) { g_rowptr[idx] = off; off += g_degi[idx]; }
    }
    if (t == 1023) g_rowptr[NN] = off;
}

__global__ void __launch_bounds__(256) k_scatter(const int* __restrict__ src,
                                                 const int* __restrict__ dst) {
    int e = blockIdx.x * 256 + threadIdx.x;   // grid exactly EE/256
    int d = dst[e];
    int pos = g_rowptr[d] + atomicAdd(&g_cnt[d], 1);
    g_cs[pos]  = src[e];
    g_ct1[pos] = g_t1[e];
    g_ct2[pos] = g_t2[e];
}

// ---------------- tiled GEMM: g_h = xin @ W  (32 rows x 64 cols per tile) ----------------
template <int DIN, int SRC>
__global__ void __launch_bounds__(256) k_gemm(const float* __restrict__ xin_p,
                                              const float* __restrict__ W) {
    __shared__ float Ws[DIN * HH];
    __shared__ float Xs[32 * DIN];
    const float* xin = SRC ? g_x1 : xin_p;
    int tid = threadIdx.x;
    for (int i = tid; i < DIN * HH / 4; i += 256)
        ((float4*)Ws)[i] = ((const float4*)W)[i];

    const int NT = (NN + 31) / 32;
    int tx = tid & 15, ty = tid >> 4;
    int ra = 2 * ty, rb = 2 * ty + 1;

    for (int t = blockIdx.x; t < NT; t += gridDim.x) {
        __syncthreads();     // W ready (1st iter) / previous compute done
        int r0g = t * 32;
        for (int i = tid; i < 32 * DIN / 4; i += 256) {
            int r = i / (DIN / 4), q = i % (DIN / 4);
            float4 vv = (r0g + r < NN) ? ((const float4*)(xin + (size_t)(r0g + r) * DIN))[q]
                                       : make_float4(0.f, 0.f, 0.f, 0.f);
            ((float4*)Xs)[i] = vv;
        }
        __syncthreads();
        float4 aA = {0,0,0,0}, aB = {0,0,0,0};
        #pragma unroll 8
        for (int k = 0; k < DIN; k++) {
            float xa = Xs[ra * DIN + k], xb = Xs[rb * DIN + k];
            float4 wv = ((float4*)Ws)[k * 16 + tx];
            aA.x = fmaf(xa, wv.x, aA.x); aA.y = fmaf(xa, wv.y, aA.y);
            aA.z = fmaf(xa, wv.z, aA.z); aA.w = fmaf(xa, wv.w, aA.w);
            aB.x = fmaf(xb, wv.x, aB.x); aB.y = fmaf(xb, wv.y, aB.y);
            aB.z = fmaf(xb, wv.z, aB.z); aB.w = fmaf(xb, wv.w, aB.w);
        }
        int gA = r0g + ra, gB = r0g + rb;
        if (gA < NN) ((float4*)(g_h + (size_t)gA * HH))[tx] = aA;
        if (gB < NN) ((float4*)(g_h + (size_t)gB * HH))[tx] = aB;
    }
}

// s_src = h . a_src, s_dst = h . a_dst   (8 nodes per 256-thread block)
__global__ void __launch_bounds__(256) k_scores(const float* __restrict__ as,
                                                const float* __restrict__ ad) {
    int tid = threadIdx.x, lane = tid & 31;
    int n = blockIdx.x * 8 + (tid >> 5);      // grid exactly NN/8
    float h1 = g_h[(size_t)n * HH + lane], h2 = g_h[(size_t)n * HH + 32 + lane];
    float ps = h1 * as[lane] + h2 * as[32 + lane];
    float pd = h1 * ad[lane] + h2 * ad[32 + lane];
    #pragma unroll
    for (int o = 16; o > 0; o >>= 1) {
        ps += __shfl_xor_sync(0xffffffffu, ps, o);
        pd += __shfl_xor_sync(0xffffffffu, pd, o);
    }
    if (lane == 0) { g_ssrc[n] = ps; g_sdst[n] = pd; }
}

// per-dst-node softmax + weighted aggregation, 64 threads / node, no atomics
__global__ void __launch_bounds__(64) k_attn(int layer, const float* __restrict__ b) {
    __shared__ float red[2][2];
    int n = blockIdx.x, tid = threadIdx.x;
    const float* ct = layer ? g_ct2 : g_ct1;
    float* xout = layer ? g_x2 : g_x1;
    int beg = g_rowptr[n], end = g_rowptr[n + 1];
    int deg = end - beg;
    float sd = g_sdst[n], ss = g_ssrc[n];

    float mloc = -1e30f, tsum = 0.f;
    for (int j = beg + tid; j < end; j += 64) {
        float t = ct[j];
        float l = lrelu(g_ssrc[g_cs[j]] + sd + t);
        g_scr[j] = l;
        tsum += t;
        mloc = fmaxf(mloc, l);
    }
    #pragma unroll
    for (int o = 16; o > 0; o >>= 1) {
        mloc = fmaxf(mloc, __shfl_xor_sync(0xffffffffu, mloc, o));
        tsum += __shfl_xor_sync(0xffffffffu, tsum, o);
    }
    if ((tid & 31) == 0) { red[tid >> 5][0] = mloc; red[tid >> 5][1] = tsum; }
    __syncthreads();
    mloc = fmaxf(red[0][0], red[1][0]);
    tsum = red[0][1] + red[1][1];

    float tl = tsum / fmaxf((float)deg, 1.0f);
    float lself = lrelu(ss + sd + tl);
    float m = fmaxf(mloc, lself);

    float ssum = 0.f;
    for (int j = beg + tid; j < end; j += 64) {
        float ev = __expf(g_scr[j] - m);
        g_scr[j] = ev;
        ssum += ev;
    }
    #pragma unroll
    for (int o = 16; o > 0; o >>= 1) ssum += __shfl_xor_sync(0xffffffffu, ssum, o);
    __syncthreads();                 // scr visible + red reusable
    if ((tid & 31) == 0) red[tid >> 5][0] = ssum;
    __syncthreads();
    float denom = red[0][0] + red[1][0] + __expf(lself - m);
    float inv = 1.f / denom;

    int c = tid;
    float acc = 0.f;
    for (int j = beg; j < end; j++) {
        int s = g_cs[j];             // broadcast
        acc = fmaf(g_scr[j], g_h[(size_t)s * HH + c], acc);
    }
    float aself = __expf(lself - m) * inv;
    float val = acc * inv + aself * g_h[(size_t)n * HH + c] + b[c];
    xout[(size_t)n * HH + c] = fmaxf(val, 0.f);
}

// ---------------- classifier ----------------
// u = x2 @ Wc1[0:64], v = x2 @ Wc1[64:128]  (tiled like k_gemm)
__global__ void __launch_bounds__(256) k_gemm_uv(const float* __restrict__ Wc1) {
    __shared__ float Wu[HH * HH];
    __shared__ float Wv[HH * HH];
    __shared__ float Xs[32 * HH];
    int tid = threadIdx.x;
    for (int i = tid; i < HH * HH / 4; i += 256) {
        ((float4*)Wu)[i] = ((const float4*)Wc1)[i];
        ((float4*)Wv)[i] = ((const float4*)(Wc1 + HH * HH))[i];
    }
    const int NT = (NN + 31) / 32;
    int tx = tid & 15, ty = tid >> 4;
    int ra = 2 * ty, rb = 2 * ty + 1;
    for (int t = blockIdx.x; t < NT; t += gridDim.x) {
        __syncthreads();
        int r0g = t * 32;
        for (int i = tid; i < 32 * HH / 4; i += 256) {
            int r = i / (HH / 4), q = i % (HH / 4);
            float4 vv = (r0g + r < NN) ? ((const float4*)(g_x2 + (size_t)(r0g + r) * HH))[q]
                                       : make_float4(0.f, 0.f, 0.f, 0.f);
            ((float4*)Xs)[i] = vv;
        }
        __syncthreads();
        float4 uA = {0,0,0,0}, uB = {0,0,0,0}, vA = {0,0,0,0}, vB = {0,0,0,0};
        #pragma unroll 8
        for (int k = 0; k < HH; k++) {
            float xa = Xs[ra * HH + k], xb = Xs[rb * HH + k];
            float4 wu = ((float4*)Wu)[k * 16 + tx];
            float4 wv = ((float4*)Wv)[k * 16 + tx];
            uA.x = fmaf(xa, wu.x, uA.x); uA.y = fmaf(xa, wu.y, uA.y);
            uA.z = fmaf(xa, wu.z, uA.z); uA.w = fmaf(xa, wu.w, uA.w);
            uB.x = fmaf(xb, wu.x, uB.x); uB.y = fmaf(xb, wu.y, uB.y);
            uB.z = fmaf(xb, wu.z, uB.z); uB.w = fmaf(xb, wu.w, uB.w);
            vA.x = fmaf(xa, wv.x, vA.x); vA.y = fmaf(xa, wv.y, vA.y);
            vA.z = fmaf(xa, wv.z, vA.z); vA.w = fmaf(xa, wv.w, vA.w);
            vB.x = fmaf(xb, wv.x, vB.x); vB.y = fmaf(xb, wv.y, vB.y);
            vB.z = fmaf(xb, wv.z, vB.z); vB.w = fmaf(xb, wv.w, vB.w);
        }
        int gA = r0g + ra, gB = r0g + rb;
        if (gA < NN) {
            ((float4*)(g_u + (size_t)gA * HH))[tx] = uA;
            ((float4*)(g_v + (size_t)gA * HH))[tx] = vA;
        }
        if (gB < NN) {
            ((float4*)(g_u + (size_t)gB * HH))[tx] = uB;
            ((float4*)(g_v + (size_t)gB * HH))[tx] = vB;
        }
    }
}

// persistent fused per-edge classifier: Wb column cached in regs
__global__ void __launch_bounds__(256) k_classify(const int* __restrict__ src,
                                                  const int* __restrict__ dst,
                                                  const float* __restrict__ ea,
                                                  const float* __restrict__ Wc1,
                                                  const float* __restrict__ bc1,
                                                  const float* __restrict__ Wc2,
                                                  const float* __restrict__ bc2,
                                                  float* __restrict__ out) {
    __shared__ float eas[4][DE];
    __shared__ float red[8];
    int tid = threadIdx.x, c = tid & 63, g = tid >> 6;
    float wcol[DE];
    #pragma unroll
    for (int k = 0; k < DE; k++) wcol[k] = Wc1[2 * HH * HH + k * HH + c];
    float wc2c = Wc2[c], b1c = bc1[c], b2 = bc2[0];

    for (int eb = blockIdx.x * 4; eb < EE; eb += gridDim.x * 4) {
        int e = eb + g;                       // eb ≡ 0 mod 4 and < EE  ->  e < EE
        if (c < DE) eas[g][c] = ea[(size_t)e * DE + c];
        __syncthreads();
        int s = src[e], d = dst[e];
        float acc = g_u[(size_t)s * HH + c] + g_v[(size_t)d * HH + c] + b1c;
        #pragma unroll
        for (int k = 0; k < DE; k++) acc = fmaf(eas[g][k], wcol[k], acc);
        acc = fmaxf(acc, 0.f) * wc2c;
        #pragma unroll
        for (int o = 16; o > 0; o >>= 1) acc += __shfl_down_sync(0xffffffffu, acc, o);
        if ((tid & 31) == 0) red[tid >> 5] = acc;
        __syncthreads();
        if (c == 0) out[e] = red[2 * g] + red[2 * g + 1] + b2;
    }
}

// ---------------- host launcher ----------------
extern "C" void kernel_launch(void* const* d_in, const int* in_sizes, int n_in,
                              void* d_out, int out_size) {
    const float* x    = (const float*)d_in[0];
    const int*   ei   = (const int*)  d_in[1];
    const float* ea   = (const float*)d_in[2];
    const float* W1   = (const float*)d_in[3];
    const float* We1  = (const float*)d_in[4];
    const float* as1  = (const float*)d_in[5];
    const float* ad1  = (const float*)d_in[6];
    const float* ae1  = (const float*)d_in[7];
    const float* b1   = (const float*)d_in[8];
    const float* W2   = (const float*)d_in[9];
    const float* We2  = (const float*)d_in[10];
    const float* as2  = (const float*)d_in[11];
    const float* ad2  = (const float*)d_in[12];
    const float* ae2  = (const float*)d_in[13];
    const float* b2   = (const float*)d_in[14];
    const float* Wc1  = (const float*)d_in[15];
    const float* bc1  = (const float*)d_in[16];
    const float* Wc2  = (const float*)d_in[17];
    const float* bc2  = (const float*)d_in[18];
    float*       out  = (float*)d_out;

    const int* src = ei;        // edge_index[0]
    const int* dst = ei + EE;   // edge_index[1]

    const int NB_N = (NN + 255) / 256;
    const int NB_E = EE / 256;          // exact
    const int GEMM_GRID = 740;
    const int CLS_GRID  = 1480;

    // graph prep (once)
    k_prep<<<1, 32>>>(We1, ae1, We2, ae2);
    k_zero<<<NB_N, 256>>>();
    k_edge_t<<<NB_E, 256>>>(ea, dst);
    k_scan<<<1, 1024>>>();
    k_scatter<<<NB_E, 256>>>(src, dst);

    // ---- GAT layer 1 ----
    k_gemm<D0, 0><<<GEMM_GRID, 256>>>(x, W1);
    k_scores<<<NN / 8, 256>>>(as1, ad1);
    k_attn<<<NN, 64>>>(0, b1);

    // ---- GAT layer 2 ----
    k_gemm<HH, 1><<<GEMM_GRID, 256>>>(nullptr, W2);
    k_scores<<<NN / 8, 256>>>(as2, ad2);
    k_attn<<<NN, 64>>>(1, b2);

    // ---- edge classifier ----
    k_gemm_uv<<<GEMM_GRID, 256>>>(Wc1);
    k_classify<<<CLS_GRID, 256>>>(src, dst, ea, Wc1, bc1, Wc2, bc2, out);
}

// round 3
// speedup vs baseline: 2.4028x; 1.3089x over previous
#include <cuda_runtime.h>

#define NN 50000
#define EE 800000
#define HH 64
#define D0 128
#define DE 32
#define NEG 0.2f

typedef unsigned long long ull;

// ---------------- scratch (static device globals; no allocation) ----------------
__device__ __align__(16) float g_h  [NN * HH];
__device__ __align__(16) float g_x1 [NN * HH];
__device__ __align__(16) float g_x2 [NN * HH];
__device__ __align__(16) float g_u  [NN * HH];
__device__ __align__(16) float g_v  [NN * HH];
__device__ float g_ssrc[NN], g_sdst[NN];
__device__ int   g_degi[NN];
__device__ int   g_rowptr[NN + 1];
__device__ int   g_cnt[NN];
__device__ int   g_bsum[128], g_boff[128];
__device__ int   g_cs [EE];            // src ids, CSR (by dst) order
__device__ float g_ct1[EE], g_ct2[EE]; // t_e per layer, CSR order
__device__ float g_t1[EE], g_t2[EE];   // t_e per layer, original order
__device__ float g_wv1[DE], g_wv2[DE];

__device__ __forceinline__ float lrelu(float z) { return z >= 0.f ? z : NEG * z; }

// ---- packed f32x2 helpers (Blackwell FFMA2 path) ----
__device__ __forceinline__ ull pk2(float x, float y) {
    ull r; asm("mov.b64 %0, {%1,%2};" : "=l"(r) : "f"(x), "f"(y)); return r;
}
__device__ __forceinline__ void fma2(ull& d, ull a, ull b) {
    asm("fma.rn.f32x2 %0, %1, %2, %0;" : "+l"(d) : "l"(a), "l"(b));
}
__device__ __forceinline__ ull add2(ull a, ull b) {
    ull r; asm("add.rn.f32x2 %0, %1, %2;" : "=l"(r) : "l"(a), "l"(b)); return r;
}
__device__ __forceinline__ float2 upk2(ull v) {
    float2 f; asm("mov.b64 {%0,%1}, %2;" : "=f"(f.x), "=f"(f.y) : "l"(v)); return f;
}

// ---------------- wv = We @ a_edge ----------------
__global__ void k_prep(const float* __restrict__ We1, const float* __restrict__ ae1,
                       const float* __restrict__ We2, const float* __restrict__ ae2) {
    int k = threadIdx.x;   // 32 threads
    float s1 = 0.f, s2 = 0.f;
    #pragma unroll 8
    for (int j = 0; j < HH; j++) {
        s1 = fmaf(We1[k * HH + j], ae1[j], s1);
        s2 = fmaf(We2[k * HH + j], ae2[j], s2);
    }
    g_wv1[k] = s1;
    g_wv2[k] = s2;
}

__global__ void k_zero() {
    int i = blockIdx.x * blockDim.x + threadIdx.x;
    if (i < NN) { g_degi[i] = 0; g_cnt[i] = 0; }
}

// t_e for both layers + degree histogram
__global__ void __launch_bounds__(256) k_edge_t(const float* __restrict__ ea,
                                                const int* __restrict__ dst) {
    __shared__ float wv1s[DE], wv2s[DE];
    int tid = threadIdx.x;
    if (tid < DE) { wv1s[tid] = g_wv1[tid]; wv2s[tid] = g_wv2[tid]; }
    __syncthreads();
    int e = blockIdx.x * 256 + tid;           // grid exactly EE/256
    const float4* p = (const float4*)(ea + (size_t)e * DE);
    float t1 = 0.f, t2 = 0.f;
    #pragma unroll
    for (int q = 0; q < 8; q++) {
        float4 v = p[q];
        t1 = fmaf(v.x, wv1s[4*q+0], t1); t1 = fmaf(v.y, wv1s[4*q+1], t1);
        t1 = fmaf(v.z, wv1s[4*q+2], t1); t1 = fmaf(v.w, wv1s[4*q+3], t1);
        t2 = fmaf(v.x, wv2s[4*q+0], t2); t2 = fmaf(v.y, wv2s[4*q+1], t2);
        t2 = fmaf(v.z, wv2s[4*q+2], t2); t2 = fmaf(v.w, wv2s[4*q+3], t2);
    }
    g_t1[e] = t1;
    g_t2[e] = t2;
    atomicAdd(&g_degi[dst[e]], 1);
}

// ---------------- parallel scan: degi -> rowptr ----------------
#define SCAN_B 512
#define SCAN_G 98          // 98*512 = 50176 >= NN

__global__ void __launch_bounds__(SCAN_B) k_scanA() {
    __shared__ int ws[SCAN_B / 32];
    int idx = blockIdx.x * SCAN_B + threadIdx.x;
    int v = (idx < NN) ? g_degi[idx] : 0;
    int s = v;
    #pragma unroll
    for (int o = 16; o > 0; o >>= 1) s += __shfl_xor_sync(0xffffffffu, s, o);
    if ((threadIdx.x & 31) == 0) ws[threadIdx.x >> 5] = s;
    __syncthreads();
    if (threadIdx.x < SCAN_B / 32) {
        int t = ws[threadIdx.x];
        #pragma unroll
        for (int o = 8; o > 0; o >>= 1) t += __shfl_xor_sync(0xffffu, t, o);
        if (threadIdx.x == 0) g_bsum[blockIdx.x] = t;
    }
}

__global__ void k_scanB() {
    __shared__ int s[SCAN_G];
    int t = threadIdx.x;        // 128 threads
    if (t < SCAN_G) s[t] = g_bsum[t];
    __syncthreads();
    if (t == 0) {
        int run = 0;
        for (int i = 0; i < SCAN_G; i++) { int x = s[i]; s[i] = run; run += x; }
        g_rowptr[NN] = run;
    }
    __syncthreads();
    if (t < SCAN_G) g_boff[t] = s[t];
}

__global__ void __launch_bounds__(SCAN_B) k_scanC() {
    __shared__ int ws[SCAN_B / 32];
    int lane = threadIdx.x & 31, w = threadIdx.x >> 5;
    int idx = blockIdx.x * SCAN_B + threadIdx.x;
    int v = (idx < NN) ? g_degi[idx] : 0;
    int inc = v;
    #pragma unroll
    for (int o = 1; o < 32; o <<= 1) {
        int x = __shfl_up_sync(0xffffffffu, inc, o);
        if (lane >= o) inc += x;
    }
    if (lane == 31) ws[w] = inc;
    __syncthreads();
    if (w == 0 && lane < SCAN_B / 32) {
        int y = ws[lane];
        #pragma unroll
        for (int o = 1; o < SCAN_B / 32; o <<= 1) {
            int x = __shfl_up_sync(0xffffu, y, o);
            if (lane >= o) y += x;
        }
        ws[lane] = y;
    }
    __syncthreads();
    int off = inc - v + (w > 0 ? ws[w - 1] : 0) + g_boff[blockIdx.x];
    if (idx < NN) g_rowptr[idx] = off;
}

__global__ void __launch_bounds__(256) k_scatter(const int* __restrict__ src,
                                                 const int* __restrict__ dst) {
    int e = blockIdx.x * 256 + threadIdx.x;   // grid exactly EE/256
    int d = dst[e];
    int pos = g_rowptr[d] + atomicAdd(&g_cnt[d], 1);
    g_cs[pos]  = src[e];
    g_ct1[pos] = g_t1[e];
    g_ct2[pos] = g_t2[e];
}

// ---------------- tiled GEMM: g_h = xin @ W  (32 rows x 64 cols per tile) ----------------
template <int DIN, int SRC>
__global__ void __launch_bounds__(256) k_gemm(const float* __restrict__ xin_p,
                                              const float* __restrict__ W) {
    __shared__ float Ws[DIN * HH];
    __shared__ float Xs[32 * DIN];
    const float* xin = SRC ? g_x1 : xin_p;
    int tid = threadIdx.x;
    for (int i = tid; i < DIN * HH / 4; i += 256)
        ((float4*)Ws)[i] = ((const float4*)W)[i];

    const int NT = (NN + 31) / 32;
    int tx = tid & 15, ty = tid >> 4;
    int ra = 2 * ty, rb = 2 * ty + 1;

    for (int t = blockIdx.x; t < NT; t += gridDim.x) {
        __syncthreads();
        int r0g = t * 32;
        for (int i = tid; i < 32 * DIN / 4; i += 256) {
            int r = i / (DIN / 4), q = i % (DIN / 4);
            float4 vv = (r0g + r < NN) ? ((const float4*)(xin + (size_t)(r0g + r) * DIN))[q]
                                       : make_float4(0.f, 0.f, 0.f, 0.f);
            ((float4*)Xs)[i] = vv;
        }
        __syncthreads();
        float4 aA = {0,0,0,0}, aB = {0,0,0,0};
        #pragma unroll 8
        for (int k = 0; k < DIN; k++) {
            float xa = Xs[ra * DIN + k], xb = Xs[rb * DIN + k];
            float4 wv = ((float4*)Ws)[k * 16 + tx];
            aA.x = fmaf(xa, wv.x, aA.x); aA.y = fmaf(xa, wv.y, aA.y);
            aA.z = fmaf(xa, wv.z, aA.z); aA.w = fmaf(xa, wv.w, aA.w);
            aB.x = fmaf(xb, wv.x, aB.x); aB.y = fmaf(xb, wv.y, aB.y);
            aB.z = fmaf(xb, wv.z, aB.z); aB.w = fmaf(xb, wv.w, aB.w);
        }
        int gA = r0g + ra, gB = r0g + rb;
        if (gA < NN) ((float4*)(g_h + (size_t)gA * HH))[tx] = aA;
        if (gB < NN) ((float4*)(g_h + (size_t)gB * HH))[tx] = aB;
    }
}

// s_src = h . a_src, s_dst = h . a_dst   (8 nodes per 256-thread block)
__global__ void __launch_bounds__(256) k_scores(const float* __restrict__ as,
                                                const float* __restrict__ ad) {
    int tid = threadIdx.x, lane = tid & 31;
    int n = blockIdx.x * 8 + (tid >> 5);      // grid exactly NN/8
    float h1 = g_h[(size_t)n * HH + lane], h2 = g_h[(size_t)n * HH + 32 + lane];
    float ps = h1 * as[lane] + h2 * as[32 + lane];
    float pd = h1 * ad[lane] + h2 * ad[32 + lane];
    #pragma unroll
    for (int o = 16; o > 0; o >>= 1) {
        ps += __shfl_xor_sync(0xffffffffu, ps, o);
        pd += __shfl_xor_sync(0xffffffffu, pd, o);
    }
    if (lane == 0) { g_ssrc[n] = ps; g_sdst[n] = pd; }
}

// per-dst-node softmax + aggregation: ONE WARP per node, f32x2, no barriers
__global__ void __launch_bounds__(256) k_attn(int layer, const float* __restrict__ b) {
    int lane = threadIdx.x & 31;
    int n = blockIdx.x * 8 + (threadIdx.x >> 5);   // grid exactly NN/8
    const float* ct = layer ? g_ct2 : g_ct1;
    float* xout = layer ? g_x2 : g_x1;
    int beg = g_rowptr[n], end = g_rowptr[n + 1];
    float sd = g_sdst[n], ss = g_ssrc[n];

    // pass1: running max of logits + sum of t (for mean self-loop attr)
    float mloc = -1e30f, tsum = 0.f;
    #pragma unroll 4
    for (int j = beg + lane; j < end; j += 32) {
        float t = ct[j];
        float l = lrelu(g_ssrc[g_cs[j]] + sd + t);
        mloc = fmaxf(mloc, l);
        tsum += t;
    }
    #pragma unroll
    for (int o = 16; o > 0; o >>= 1) {
        mloc = fmaxf(mloc, __shfl_xor_sync(0xffffffffu, mloc, o));
        tsum += __shfl_xor_sync(0xffffffffu, tsum, o);
    }
    float deg = (float)(end - beg);
    float tl = tsum / fmaxf(deg, 1.0f);
    float lself = lrelu(ss + sd + tl);
    float m = fmaxf(mloc, lself);

    // pass2: chunked — each lane computes exp for one edge, shfl-broadcast,
    // all lanes accumulate 2 columns via FFMA2
    const ull* h2 = (const ull*)g_h;
    ull acc2 = pk2(0.f, 0.f);
    float ssum = 0.f;
    for (int base = beg; base < end; base += 32) {
        int j = base + lane;
        float ev = 0.f; int si = 0;
        if (j < end) {
            si = g_cs[j];
            ev = __expf(lrelu(g_ssrc[si] + sd + ct[j]) - m);
        }
        ssum += ev;
        int cnt = min(32, end - base);
        #pragma unroll 4
        for (int k = 0; k < cnt; k++) {
            int   s = __shfl_sync(0xffffffffu, si, k);
            float w = __shfl_sync(0xffffffffu, ev, k);
            ull hv = h2[(size_t)s * 32 + lane];
            fma2(acc2, pk2(w, w), hv);
        }
    }
    #pragma unroll
    for (int o = 16; o > 0; o >>= 1) ssum += __shfl_xor_sync(0xffffffffu, ssum, o);

    float eself = __expf(lself - m);
    float inv = 1.f / (ssum + eself);
    float aself = eself * inv;

    float2 a = upk2(acc2);
    float2 hn = upk2(((const ull*)g_h)[(size_t)n * 32 + lane]);
    float2 bv = ((const float2*)b)[lane];
    float2 o2;
    o2.x = fmaxf(fmaf(a.x, inv, fmaf(aself, hn.x, bv.x)), 0.f);
    o2.y = fmaxf(fmaf(a.y, inv, fmaf(aself, hn.y, bv.y)), 0.f);
    ((float2*)xout)[(size_t)n * 32 + lane] = o2;
}

// ---------------- classifier ----------------
// u = x2 @ Wc1[0:64], v = x2 @ Wc1[64:128]
__global__ void __launch_bounds__(256) k_gemm_uv(const float* __restrict__ Wc1) {
    __shared__ float Wu[HH * HH];
    __shared__ float Wv[HH * HH];
    __shared__ float Xs[32 * HH];
    int tid = threadIdx.x;
    for (int i = tid; i < HH * HH / 4; i += 256) {
        ((float4*)Wu)[i] = ((const float4*)Wc1)[i];
        ((float4*)Wv)[i] = ((const float4*)(Wc1 + HH * HH))[i];
    }
    const int NT = (NN + 31) / 32;
    int tx = tid & 15, ty = tid >> 4;
    int ra = 2 * ty, rb = 2 * ty + 1;
    for (int t = blockIdx.x; t < NT; t += gridDim.x) {
        __syncthreads();
        int r0g = t * 32;
        for (int i = tid; i < 32 * HH / 4; i += 256) {
            int r = i / (HH / 4), q = i % (HH / 4);
            float4 vv = (r0g + r < NN) ? ((const float4*)(g_x2 + (size_t)(r0g + r) * HH))[q]
                                       : make_float4(0.f, 0.f, 0.f, 0.f);
            ((float4*)Xs)[i] = vv;
        }
        __syncthreads();
        float4 uA = {0,0,0,0}, uB = {0,0,0,0}, vA = {0,0,0,0}, vB = {0,0,0,0};
        #pragma unroll 8
        for (int k = 0; k < HH; k++) {
            float xa = Xs[ra * HH + k], xb = Xs[rb * HH + k];
            float4 wu = ((float4*)Wu)[k * 16 + tx];
            float4 wv = ((float4*)Wv)[k * 16 + tx];
            uA.x = fmaf(xa, wu.x, uA.x); uA.y = fmaf(xa, wu.y, uA.y);
            uA.z = fmaf(xa, wu.z, uA.z); uA.w = fmaf(xa, wu.w, uA.w);
            uB.x = fmaf(xb, wu.x, uB.x); uB.y = fmaf(xb, wu.y, uB.y);
            uB.z = fmaf(xb, wu.z, uB.z); uB.w = fmaf(xb, wu.w, uB.w);
            vA.x = fmaf(xa, wv.x, vA.x); vA.y = fmaf(xa, wv.y, vA.y);
            vA.z = fmaf(xa, wv.z, vA.z); vA.w = fmaf(xa, wv.w, vA.w);
            vB.x = fmaf(xb, wv.x, vB.x); vB.y = fmaf(xb, wv.y, vB.y);
            vB.z = fmaf(xb, wv.z, vB.z); vB.w = fmaf(xb, wv.w, vB.w);
        }
        int gA = r0g + ra, gB = r0g + rb;
        if (gA < NN) {
            ((float4*)(g_u + (size_t)gA * HH))[tx] = uA;
            ((float4*)(g_v + (size_t)gA * HH))[tx] = vA;
        }
        if (gB < NN) {
            ((float4*)(g_u + (size_t)gB * HH))[tx] = uB;
            ((float4*)(g_v + (size_t)gB * HH))[tx] = vB;
        }
    }
}

// persistent warp-per-edge classifier, f32x2, warp-local reductions only
__global__ void __launch_bounds__(256) k_classify(const int* __restrict__ src,
                                                  const int* __restrict__ dst,
                                                  const float* __restrict__ ea,
                                                  const float* __restrict__ Wc1,
                                                  const float* __restrict__ bc1,
                                                  const float* __restrict__ Wc2,
                                                  const float* __restrict__ bc2,
                                                  float* __restrict__ out) {
    __shared__ float eas[8][DE];
    int tid = threadIdx.x, lane = tid & 31, w = tid >> 5;

    // lane owns output columns 2*lane, 2*lane+1
    ull wcol2[DE];
    #pragma unroll
    for (int k = 0; k < DE; k++)
        wcol2[k] = ((const ull*)(Wc1 + 2 * HH * HH + k * HH))[lane];
    ull  b1v  = ((const ull*)bc1)[lane];
    float2 wc2v = ((const float2*)Wc2)[lane];
    float b2 = bc2[0];

    const ull* u2p = (const ull*)g_u;
    const ull* v2p = (const ull*)g_v;

    for (int eb = blockIdx.x * 8; eb < EE; eb += gridDim.x * 8) {
        int e = eb + w;                     // EE % 8 == 0
        eas[w][lane] = ea[(size_t)e * DE + lane];
        __syncwarp();
        int s = src[e], d = dst[e];
        ull acc2 = add2(add2(u2p[(size_t)s * 32 + lane], v2p[(size_t)d * 32 + lane]), b1v);
        #pragma unroll
        for (int k = 0; k < DE; k += 2) {
            float2 e2 = *(const float2*)&eas[w][k];
            fma2(acc2, pk2(e2.x, e2.x), wcol2[k]);
            fma2(acc2, pk2(e2.y, e2.y), wcol2[k + 1]);
        }
        float2 a = upk2(acc2);
        float r = fmaxf(a.x, 0.f) * wc2v.x + fmaxf(a.y, 0.f) * wc2v.y;
        #pragma unroll
        for (int o = 16; o > 0; o >>= 1) r += __shfl_xor_sync(0xffffffffu, r, o);
        if (lane == 0) out[e] = r + b2;
        __syncwarp();
    }
}

// ---------------- host launcher ----------------
extern "C" void kernel_launch(void* const* d_in, const int* in_sizes, int n_in,
                              void* d_out, int out_size) {
    const float* x    = (const float*)d_in[0];
    const int*   ei   = (const int*)  d_in[1];
    const float* ea   = (const float*)d_in[2];
    const float* W1   = (const float*)d_in[3];
    const float* We1  = (const float*)d_in[4];
    const float* as1  = (const float*)d_in[5];
    const float* ad1  = (const float*)d_in[6];
    const float* ae1  = (const float*)d_in[7];
    const float* b1   = (const float*)d_in[8];
    const float* W2   = (const float*)d_in[9];
    const float* We2  = (const float*)d_in[10];
    const float* as2  = (const float*)d_in[11];
    const float* ad2  = (const float*)d_in[12];
    const float* ae2  = (const float*)d_in[13];
    const float* b2   = (const float*)d_in[14];
    const float* Wc1  = (const float*)d_in[15];
    const float* bc1  = (const float*)d_in[16];
    const float* Wc2  = (const float*)d_in[17];
    const float* bc2  = (const float*)d_in[18];
    float*       out  = (float*)d_out;

    const int* src = ei;        // edge_index[0]
    const int* dst = ei + EE;   // edge_index[1]

    const int NB_N = (NN + 255) / 256;
    const int NB_E = EE / 256;          // exact
    const int GEMM_GRID = 740;
    const int CLS_GRID  = 296;

    // graph prep (once)
    k_prep<<<1, 32>>>(We1, ae1, We2, ae2);
    k_zero<<<NB_N, 256>>>();
    k_edge_t<<<NB_E, 256>>>(ea, dst);
    k_scanA<<<SCAN_G, SCAN_B>>>();
    k_scanB<<<1, 128>>>();
    k_scanC<<<SCAN_G, SCAN_B>>>();
    k_scatter<<<NB_E, 256>>>(src, dst);

    // ---- GAT layer 1 ----
    k_gemm<D0, 0><<<GEMM_GRID, 256>>>(x, W1);
    k_scores<<<NN / 8, 256>>>(as1, ad1);
    k_attn<<<NN / 8, 256>>>(0, b1);

    // ---- GAT layer 2 ----
    k_gemm<HH, 1><<<GEMM_GRID, 256>>>(nullptr, W2);
    k_scores<<<NN / 8, 256>>>(as2, ad2);
    k_attn<<<NN / 8, 256>>>(1, b2);

    // ---- edge classifier ----
    k_gemm_uv<<<GEMM_GRID, 256>>>(Wc1);
    k_classify<<<CLS_GRID, 256>>>(src, dst, ea, Wc1, bc1, Wc2, bc2, out);
}

// round 4
// speedup vs baseline: 2.4938x; 1.0379x over previous
#include <cuda_runtime.h>

#define NN 50000
#define EE 800000
#define HH 64
#define D0 128
#define DE 32
#define NEG 0.2f

typedef unsigned long long ull;

// ---------------- scratch (static device globals; no allocation) ----------------
__device__ __align__(16) float g_h  [NN * HH];
__device__ __align__(16) float g_x1 [NN * HH];
__device__ __align__(16) float g_x2 [NN * HH];
__device__ __align__(16) float g_u  [NN * HH];
__device__ __align__(16) float g_v  [NN * HH];
__device__ float g_ssrc[NN], g_sdst[NN];
__device__ int   g_degi[NN];
__device__ int   g_rowptr[NN + 1];
__device__ int   g_cnt[NN];
__device__ int   g_bsum[128];
__device__ int   g_cs [EE];            // src ids, CSR (by dst) order
__device__ float g_ct1[EE], g_ct2[EE]; // t_e per layer, CSR order
__device__ float g_t1[EE], g_t2[EE];   // t_e per layer, original order
__device__ float g_wv1[DE], g_wv2[DE];

__device__ __forceinline__ float lrelu(float z) { return z >= 0.f ? z : NEG * z; }

// ---- packed f32x2 helpers (Blackwell FFMA2 path) ----
__device__ __forceinline__ ull pk2(float x, float y) {
    ull r; asm("mov.b64 %0, {%1,%2};" : "=l"(r) : "f"(x), "f"(y)); return r;
}
__device__ __forceinline__ void fma2(ull& d, ull a, ull b) {
    asm("fma.rn.f32x2 %0, %1, %2, %0;" : "+l"(d) : "l"(a), "l"(b));
}
__device__ __forceinline__ ull add2(ull a, ull b) {
    ull r; asm("add.rn.f32x2 %0, %1, %2;" : "=l"(r) : "l"(a), "l"(b)); return r;
}
__device__ __forceinline__ float2 upk2(ull v) {
    float2 f; asm("mov.b64 {%0,%1}, %2;" : "=f"(f.x), "=f"(f.y) : "l"(v)); return f;
}

// ---------------- zero counters + prep wv = We @ a_edge (block 0) ----------------
__global__ void k_zero_prep(const float* __restrict__ We1, const float* __restrict__ ae1,
                            const float* __restrict__ We2, const float* __restrict__ ae2) {
    int i = blockIdx.x * blockDim.x + threadIdx.x;
    if (i < NN) { g_degi[i] = 0; g_cnt[i] = 0; }
    if (i == 0) g_rowptr[NN] = EE;
    if (blockIdx.x == 0 && threadIdx.x >= 32 && threadIdx.x < 64) {
        int k = threadIdx.x - 32;
        float s1 = 0.f, s2 = 0.f;
        #pragma unroll 8
        for (int j = 0; j < HH; j++) {
            s1 = fmaf(We1[k * HH + j], ae1[j], s1);
            s2 = fmaf(We2[k * HH + j], ae2[j], s2);
        }
        g_wv1[k] = s1;
        g_wv2[k] = s2;
    }
}

// t_e for both layers + degree histogram
__global__ void __launch_bounds__(256) k_edge_t(const float* __restrict__ ea,
                                                const int* __restrict__ dst) {
    __shared__ float wv1s[DE], wv2s[DE];
    int tid = threadIdx.x;
    if (tid < DE) { wv1s[tid] = g_wv1[tid]; wv2s[tid] = g_wv2[tid]; }
    __syncthreads();
    int e = blockIdx.x * 256 + tid;           // grid exactly EE/256
    const float4* p = (const float4*)(ea + (size_t)e * DE);
    float t1 = 0.f, t2 = 0.f;
    #pragma unroll
    for (int q = 0; q < 8; q++) {
        float4 v = p[q];
        t1 = fmaf(v.x, wv1s[4*q+0], t1); t1 = fmaf(v.y, wv1s[4*q+1], t1);
        t1 = fmaf(v.z, wv1s[4*q+2], t1); t1 = fmaf(v.w, wv1s[4*q+3], t1);
        t2 = fmaf(v.x, wv2s[4*q+0], t2); t2 = fmaf(v.y, wv2s[4*q+1], t2);
        t2 = fmaf(v.z, wv2s[4*q+2], t2); t2 = fmaf(v.w, wv2s[4*q+3], t2);
    }
    g_t1[e] = t1;
    g_t2[e] = t2;
    atomicAdd(&g_degi[dst[e]], 1);
}

// ---------------- parallel scan: degi -> rowptr ----------------
#define SCAN_B 512
#define SCAN_G 98          // 98*512 = 50176 >= NN

__global__ void __launch_bounds__(SCAN_B) k_scanA() {
    __shared__ int ws[SCAN_B / 32];
    int idx = blockIdx.x * SCAN_B + threadIdx.x;
    int v = (idx < NN) ? g_degi[idx] : 0;
    int s = v;
    #pragma unroll
    for (int o = 16; o > 0; o >>= 1) s += __shfl_xor_sync(0xffffffffu, s, o);
    if ((threadIdx.x & 31) == 0) ws[threadIdx.x >> 5] = s;
    __syncthreads();
    if (threadIdx.x < SCAN_B / 32) {
        int t = ws[threadIdx.x];
        #pragma unroll
        for (int o = 8; o > 0; o >>= 1) t += __shfl_xor_sync(0xffffu, t, o);
        if (threadIdx.x == 0) g_bsum[blockIdx.x] = t;
    }
}

__global__ void __launch_bounds__(SCAN_B) k_scanC() {
    __shared__ int wsum[4];
    __shared__ int ws[SCAN_B / 32];
    __shared__ int spre;
    int tid = threadIdx.x, lane = tid & 31, w = tid >> 5;

    // block-prefix: sum of g_bsum[i] for i < blockIdx.x (SCAN_G=98 < 128)
    if (tid < 128) {
        int pv = (tid < blockIdx.x) ? g_bsum[tid] : 0;
        #pragma unroll
        for (int o = 16; o > 0; o >>= 1) pv += __shfl_xor_sync(0xffffffffu, pv, o);
        if (lane == 0) wsum[w] = pv;
    }

    int idx = blockIdx.x * SCAN_B + tid;
    int v = (idx < NN) ? g_degi[idx] : 0;
    int inc = v;
    #pragma unroll
    for (int o = 1; o < 32; o <<= 1) {
        int x = __shfl_up_sync(0xffffffffu, inc, o);
        if (lane >= o) inc += x;
    }
    if (lane == 31) ws[w] = inc;
    __syncthreads();
    if (tid == 0) spre = wsum[0] + wsum[1] + wsum[2] + wsum[3];
    if (w == 0 && lane < SCAN_B / 32) {
        int y = ws[lane];
        #pragma unroll
        for (int o = 1; o < SCAN_B / 32; o <<= 1) {
            int x = __shfl_up_sync(0xffffu, y, o);
            if (lane >= o) y += x;
        }
        ws[lane] = y;
    }
    __syncthreads();
    int off = inc - v + (w > 0 ? ws[w - 1] : 0) + spre;
    if (idx < NN) g_rowptr[idx] = off;
}

__global__ void __launch_bounds__(256) k_scatter(const int* __restrict__ src,
                                                 const int* __restrict__ dst) {
    int e = blockIdx.x * 256 + threadIdx.x;   // grid exactly EE/256
    int d = dst[e];
    int pos = g_rowptr[d] + atomicAdd(&g_cnt[d], 1);
    g_cs[pos]  = src[e];
    g_ct1[pos] = g_t1[e];
    g_ct2[pos] = g_t2[e];
}

// ---------------- tiled GEMM fused with score epilogue ----------------
// g_h = xin @ W ; g_ssrc = h.a_src ; g_sdst = h.a_dst
template <int DIN, int SRC>
__global__ void __launch_bounds__(256) k_gemm(const float* __restrict__ xin_p,
                                              const float* __restrict__ W,
                                              const float* __restrict__ as,
                                              const float* __restrict__ ad) {
    __shared__ float Ws[DIN * HH];
    __shared__ float Xs[32 * DIN];
    const float* xin = SRC ? g_x1 : xin_p;
    int tid = threadIdx.x;
    for (int i = tid; i < DIN * HH / 4; i += 256)
        ((float4*)Ws)[i] = ((const float4*)W)[i];

    const int NT = (NN + 31) / 32;
    int tx = tid & 15, ty = tid >> 4;
    int ra = 2 * ty, rb = 2 * ty + 1;
    float4 as4 = ((const float4*)as)[tx];
    float4 ad4 = ((const float4*)ad)[tx];

    for (int t = blockIdx.x; t < NT; t += gridDim.x) {
        __syncthreads();
        int r0g = t * 32;
        for (int i = tid; i < 32 * DIN / 4; i += 256) {
            int r = i / (DIN / 4), q = i % (DIN / 4);
            float4 vv = (r0g + r < NN) ? ((const float4*)(xin + (size_t)(r0g + r) * DIN))[q]
                                       : make_float4(0.f, 0.f, 0.f, 0.f);
            ((float4*)Xs)[i] = vv;
        }
        __syncthreads();
        float4 aA = {0,0,0,0}, aB = {0,0,0,0};
        #pragma unroll 8
        for (int k = 0; k < DIN; k++) {
            float xa = Xs[ra * DIN + k], xb = Xs[rb * DIN + k];
            float4 wv = ((float4*)Ws)[k * 16 + tx];
            aA.x = fmaf(xa, wv.x, aA.x); aA.y = fmaf(xa, wv.y, aA.y);
            aA.z = fmaf(xa, wv.z, aA.z); aA.w = fmaf(xa, wv.w, aA.w);
            aB.x = fmaf(xb, wv.x, aB.x); aB.y = fmaf(xb, wv.y, aB.y);
            aB.z = fmaf(xb, wv.z, aB.z); aB.w = fmaf(xb, wv.w, aB.w);
        }
        int gA = r0g + ra, gB = r0g + rb;
        if (gA < NN) ((float4*)(g_h + (size_t)gA * HH))[tx] = aA;
        if (gB < NN) ((float4*)(g_h + (size_t)gB * HH))[tx] = aB;

        // fused score epilogue: dot with a_src / a_dst, reduce across 16-lane group
        float pas = aA.x*as4.x + aA.y*as4.y + aA.z*as4.z + aA.w*as4.w;
        float pad = aA.x*ad4.x + aA.y*ad4.y + aA.z*ad4.z + aA.w*ad4.w;
        float pbs = aB.x*as4.x + aB.y*as4.y + aB.z*as4.z + aB.w*as4.w;
        float pbd = aB.x*ad4.x + aB.y*ad4.y + aB.z*ad4.z + aB.w*ad4.w;
        #pragma unroll
        for (int o = 8; o > 0; o >>= 1) {
            pas += __shfl_xor_sync(0xffffffffu, pas, o);
            pad += __shfl_xor_sync(0xffffffffu, pad, o);
            pbs += __shfl_xor_sync(0xffffffffu, pbs, o);
            pbd += __shfl_xor_sync(0xffffffffu, pbd, o);
        }
        if (tx == 0) {
            if (gA < NN) { g_ssrc[gA] = pas; g_sdst[gA] = pad; }
            if (gB < NN) { g_ssrc[gB] = pbs; g_sdst[gB] = pbd; }
        }
    }
}

// single-pass per-dst softmax + aggregation (no max subtraction: logits are O(1))
__global__ void __launch_bounds__(256) k_attn(int layer, const float* __restrict__ b) {
    int lane = threadIdx.x & 31;
    int n = blockIdx.x * 8 + (threadIdx.x >> 5);   // grid exactly NN/8
    const float* ct = layer ? g_ct2 : g_ct1;
    float* xout = layer ? g_x2 : g_x1;
    int beg = g_rowptr[n], end = g_rowptr[n + 1];
    float sd = g_sdst[n], ss = g_ssrc[n];

    const ull* h2 = (const ull*)g_h;
    ull acc2 = pk2(0.f, 0.f);
    float ssum = 0.f, tsum = 0.f;
    for (int base = beg; base < end; base += 32) {
        int j = base + lane;
        float ev = 0.f, t = 0.f; int si = 0;
        if (j < end) {
            si = g_cs[j];
            t  = ct[j];
            ev = __expf(lrelu(g_ssrc[si] + sd + t));
        }
        ssum += ev;
        tsum += t;
        int cnt = min(32, end - base);
        #pragma unroll 4
        for (int k = 0; k < cnt; k++) {
            int   s = __shfl_sync(0xffffffffu, si, k);
            float w = __shfl_sync(0xffffffffu, ev, k);
            fma2(acc2, pk2(w, w), h2[(size_t)s * 32 + lane]);
        }
    }
    #pragma unroll
    for (int o = 16; o > 0; o >>= 1) {
        ssum += __shfl_xor_sync(0xffffffffu, ssum, o);
        tsum += __shfl_xor_sync(0xffffffffu, tsum, o);
    }

    float deg = (float)(end - beg);
    float tl = tsum / fmaxf(deg, 1.0f);
    float eself = __expf(lrelu(ss + sd + tl));
    float inv = 1.f / (ssum + eself);
    float aself = eself * inv;

    float2 a = upk2(acc2);
    float2 hn = upk2(h2[(size_t)n * 32 + lane]);
    float2 bv = ((const float2*)b)[lane];
    float2 o2;
    o2.x = fmaxf(fmaf(a.x, inv, fmaf(aself, hn.x, bv.x)), 0.f);
    o2.y = fmaxf(fmaf(a.y, inv, fmaf(aself, hn.y, bv.y)), 0.f);
    ((float2*)xout)[(size_t)n * 32 + lane] = o2;
}

// ---------------- classifier ----------------
// u = x2 @ Wc1[0:64], v = x2 @ Wc1[64:128]
__global__ void __launch_bounds__(256) k_gemm_uv(const float* __restrict__ Wc1) {
    __shared__ float Wu[HH * HH];
    __shared__ float Wv[HH * HH];
    __shared__ float Xs[32 * HH];
    int tid = threadIdx.x;
    for (int i = tid; i < HH * HH / 4; i += 256) {
        ((float4*)Wu)[i] = ((const float4*)Wc1)[i];
        ((float4*)Wv)[i] = ((const float4*)(Wc1 + HH * HH))[i];
    }
    const int NT = (NN + 31) / 32;
    int tx = tid & 15, ty = tid >> 4;
    int ra = 2 * ty, rb = 2 * ty + 1;
    for (int t = blockIdx.x; t < NT; t += gridDim.x) {
        __syncthreads();
        int r0g = t * 32;
        for (int i = tid; i < 32 * HH / 4; i += 256) {
            int r = i / (HH / 4), q = i % (HH / 4);
            float4 vv = (r0g + r < NN) ? ((const float4*)(g_x2 + (size_t)(r0g + r) * HH))[q]
                                       : make_float4(0.f, 0.f, 0.f, 0.f);
            ((float4*)Xs)[i] = vv;
        }
        __syncthreads();
        float4 uA = {0,0,0,0}, uB = {0,0,0,0}, vA = {0,0,0,0}, vB = {0,0,0,0};
        #pragma unroll 8
        for (int k = 0; k < HH; k++) {
            float xa = Xs[ra * HH + k], xb = Xs[rb * HH + k];
            float4 wu = ((float4*)Wu)[k * 16 + tx];
            float4 wv = ((float4*)Wv)[k * 16 + tx];
            uA.x = fmaf(xa, wu.x, uA.x); uA.y = fmaf(xa, wu.y, uA.y);
            uA.z = fmaf(xa, wu.z, uA.z); uA.w = fmaf(xa, wu.w, uA.w);
            uB.x = fmaf(xb, wu.x, uB.x); uB.y = fmaf(xb, wu.y, uB.y);
            uB.z = fmaf(xb, wu.z, uB.z); uB.w = fmaf(xb, wu.w, uB.w);
            vA.x = fmaf(xa, wv.x, vA.x); vA.y = fmaf(xa, wv.y, vA.y);
            vA.z = fmaf(xa, wv.z, vA.z); vA.w = fmaf(xa, wv.w, vA.w);
            vB.x = fmaf(xb, wv.x, vB.x); vB.y = fmaf(xb, wv.y, vB.y);
            vB.z = fmaf(xb, wv.z, vB.z); vB.w = fmaf(xb, wv.w, vB.w);
        }
        int gA = r0g + ra, gB = r0g + rb;
        if (gA < NN) {
            ((float4*)(g_u + (size_t)gA * HH))[tx] = uA;
            ((float4*)(g_v + (size_t)gA * HH))[tx] = vA;
        }
        if (gB < NN) {
            ((float4*)(g_u + (size_t)gB * HH))[tx] = uB;
            ((float4*)(g_v + (size_t)gB * HH))[tx] = vB;
        }
    }
}

// persistent warp-per-edge classifier, f32x2, warp-local reductions only
__global__ void __launch_bounds__(256) k_classify(const int* __restrict__ src,
                                                  const int* __restrict__ dst,
                                                  const float* __restrict__ ea,
                                                  const float* __restrict__ Wc1,
                                                  const float* __restrict__ bc1,
                                                  const float* __restrict__ Wc2,
                                                  const float* __restrict__ bc2,
                                                  float* __restrict__ out) {
    __shared__ float eas[8][DE];
    int tid = threadIdx.x, lane = tid & 31, w = tid >> 5;

    // lane owns output columns 2*lane, 2*lane+1
    ull wcol2[DE];
    #pragma unroll
    for (int k = 0; k < DE; k++)
        wcol2[k] = ((const ull*)(Wc1 + 2 * HH * HH + k * HH))[lane];
    ull  b1v  = ((const ull*)bc1)[lane];
    float2 wc2v = ((const float2*)Wc2)[lane];
    float b2 = bc2[0];

    const ull* u2p = (const ull*)g_u;
    const ull* v2p = (const ull*)g_v;

    for (int eb = blockIdx.x * 8; eb < EE; eb += gridDim.x * 8) {
        int e = eb + w;                     // EE % 8 == 0
        eas[w][lane] = ea[(size_t)e * DE + lane];
        __syncwarp();
        int s = src[e], d = dst[e];
        ull acc2 = add2(add2(u2p[(size_t)s * 32 + lane], v2p[(size_t)d * 32 + lane]), b1v);
        #pragma unroll
        for (int k = 0; k < DE; k += 2) {
            float2 e2 = *(const float2*)&eas[w][k];
            fma2(acc2, pk2(e2.x, e2.x), wcol2[k]);
            fma2(acc2, pk2(e2.y, e2.y), wcol2[k + 1]);
        }
        float2 a = upk2(acc2);
        float r = fmaxf(a.x, 0.f) * wc2v.x + fmaxf(a.y, 0.f) * wc2v.y;
        #pragma unroll
        for (int o = 16; o > 0; o >>= 1) r += __shfl_xor_sync(0xffffffffu, r, o);
        if (lane == 0) out[e] = r + b2;
        __syncwarp();
    }
}

// ---------------- host launcher ----------------
extern "C" void kernel_launch(void* const* d_in, const int* in_sizes, int n_in,
                              void* d_out, int out_size) {
    const float* x    = (const float*)d_in[0];
    const int*   ei   = (const int*)  d_in[1];
    const float* ea   = (const float*)d_in[2];
    const float* W1   = (const float*)d_in[3];
    const float* We1  = (const float*)d_in[4];
    const float* as1  = (const float*)d_in[5];
    const float* ad1  = (const float*)d_in[6];
    const float* ae1  = (const float*)d_in[7];
    const float* b1   = (const float*)d_in[8];
    const float* W2   = (const float*)d_in[9];
    const float* We2  = (const float*)d_in[10];
    const float* as2  = (const float*)d_in[11];
    const float* ad2  = (const float*)d_in[12];
    const float* ae2  = (const float*)d_in[13];
    const float* b2   = (const float*)d_in[14];
    const float* Wc1  = (const float*)d_in[15];
    const float* bc1  = (const float*)d_in[16];
    const float* Wc2  = (const float*)d_in[17];
    const float* bc2  = (const float*)d_in[18];
    float*       out  = (float*)d_out;

    const int* src = ei;        // edge_index[0]
    const int* dst = ei + EE;   // edge_index[1]

    const int NB_N = (NN + 255) / 256;
    const int NB_E = EE / 256;          // exact
    const int GEMM_GRID = 740;
    const int CLS_GRID  = 296;

    // graph prep (once)
    k_zero_prep<<<NB_N, 256>>>(We1, ae1, We2, ae2);
    k_edge_t<<<NB_E, 256>>>(ea, dst);
    k_scanA<<<SCAN_G, SCAN_B>>>();
    k_scanC<<<SCAN_G, SCAN_B>>>();
    k_scatter<<<NB_E, 256>>>(src, dst);

    // ---- GAT layer 1 ----
    k_gemm<D0, 0><<<GEMM_GRID, 256>>>(x, W1, as1, ad1);
    k_attn<<<NN / 8, 256>>>(0, b1);

    // ---- GAT layer 2 ----
    k_gemm<HH, 1><<<GEMM_GRID, 256>>>(nullptr, W2, as2, ad2);
    k_attn<<<NN / 8, 256>>>(1, b2);

    // ---- edge classifier ----
    k_gemm_uv<<<GEMM_GRID, 256>>>(Wc1);
    k_classify<<<CLS_GRID, 256>>>(src, dst, ea, Wc1, bc1, Wc2, bc2, out);
}

// round 5
// speedup vs baseline: 2.7906x; 1.1190x over previous
#include <cuda_runtime.h>

#define NN 50000
#define EE 800000
#define HH 64
#define D0 128
#define DE 32
#define NEG 0.2f

typedef unsigned long long ull;

// ---------------- scratch (static device globals; no allocation) ----------------
__device__ __align__(16) float g_h  [NN * HH];
__device__ __align__(16) float g_x1 [NN * HH];
__device__ __align__(16) float g_x2 [NN * HH];
__device__ __align__(16) float g_u  [NN * HH];
__device__ __align__(16) float g_v  [NN * HH];
__device__ float g_ssrc[NN], g_sdst[NN];
__device__ int   g_degi[NN];
__device__ int   g_rowptr[NN + 1];
__device__ int   g_cnt[NN];
__device__ int   g_bsum[128];
__device__ __align__(16) float4 g_csr[EE];   // {src_bits, t1, t2, pad} per edge, CSR by dst
__device__ float g_wv1[DE], g_wv2[DE];

__device__ __forceinline__ float lrelu(float z) { return z >= 0.f ? z : NEG * z; }

// ---- packed f32x2 helpers ----
__device__ __forceinline__ ull pk2(float x, float y) {
    ull r; asm("mov.b64 %0, {%1,%2};" : "=l"(r) : "f"(x), "f"(y)); return r;
}
__device__ __forceinline__ void fma2(ull& d, ull a, ull b) {
    asm("fma.rn.f32x2 %0, %1, %2, %0;" : "+l"(d) : "l"(a), "l"(b));
}
__device__ __forceinline__ ull add2(ull a, ull b) {
    ull r; asm("add.rn.f32x2 %0, %1, %2;" : "=l"(r) : "l"(a), "l"(b)); return r;
}
__device__ __forceinline__ float2 upk2(ull v) {
    float2 f; asm("mov.b64 {%0,%1}, %2;" : "=f"(f.x), "=f"(f.y) : "l"(v)); return f;
}

// ---------------- zero counters + prep wv = We @ a_edge ----------------
__global__ void k_zero_prep(const float* __restrict__ We1, const float* __restrict__ ae1,
                            const float* __restrict__ We2, const float* __restrict__ ae2) {
    int i = blockIdx.x * blockDim.x + threadIdx.x;
    if (i < NN) { g_degi[i] = 0; g_cnt[i] = 0; }
    if (i == 0) g_rowptr[NN] = EE;
    if (blockIdx.x == 0 && threadIdx.x >= 32 && threadIdx.x < 64) {
        int k = threadIdx.x - 32;
        float s1 = 0.f, s2 = 0.f;
        #pragma unroll 8
        for (int j = 0; j < HH; j++) {
            s1 = fmaf(We1[k * HH + j], ae1[j], s1);
            s2 = fmaf(We2[k * HH + j], ae2[j], s2);
        }
        g_wv1[k] = s1;
        g_wv2[k] = s2;
    }
}

// degree histogram (dst only)
__global__ void __launch_bounds__(256) k_hist(const int* __restrict__ dst) {
    int e = blockIdx.x * 256 + threadIdx.x;   // grid exactly EE/256
    atomicAdd(&g_degi[dst[e]], 1);
}

// ---------------- parallel scan: degi -> rowptr ----------------
#define SCAN_B 512
#define SCAN_G 98          // 98*512 = 50176 >= NN

__global__ void __launch_bounds__(SCAN_B) k_scanA() {
    __shared__ int ws[SCAN_B / 32];
    int idx = blockIdx.x * SCAN_B + threadIdx.x;
    int v = (idx < NN) ? g_degi[idx] : 0;
    int s = v;
    #pragma unroll
    for (int o = 16; o > 0; o >>= 1) s += __shfl_xor_sync(0xffffffffu, s, o);
    if ((threadIdx.x & 31) == 0) ws[threadIdx.x >> 5] = s;
    __syncthreads();
    if (threadIdx.x < SCAN_B / 32) {
        int t = ws[threadIdx.x];
        #pragma unroll
        for (int o = 8; o > 0; o >>= 1) t += __shfl_xor_sync(0xffffu, t, o);
        if (threadIdx.x == 0) g_bsum[blockIdx.x] = t;
    }
}

__global__ void __launch_bounds__(SCAN_B) k_scanC() {
    __shared__ int wsum[4];
    __shared__ int ws[SCAN_B / 32];
    __shared__ int spre;
    int tid = threadIdx.x, lane = tid & 31, w = tid >> 5;
    if (tid < 128) {
        int pv = (tid < blockIdx.x) ? g_bsum[tid] : 0;
        #pragma unroll
        for (int o = 16; o > 0; o >>= 1) pv += __shfl_xor_sync(0xffffffffu, pv, o);
        if (lane == 0) wsum[w] = pv;
    }
    int idx = blockIdx.x * SCAN_B + tid;
    int v = (idx < NN) ? g_degi[idx] : 0;
    int inc = v;
    #pragma unroll
    for (int o = 1; o < 32; o <<= 1) {
        int x = __shfl_up_sync(0xffffffffu, inc, o);
        if (lane >= o) inc += x;
    }
    if (lane == 31) ws[w] = inc;
    __syncthreads();
    if (tid == 0) spre = wsum[0] + wsum[1] + wsum[2] + wsum[3];
    if (w == 0 && lane < SCAN_B / 32) {
        int y = ws[lane];
        #pragma unroll
        for (int o = 1; o < SCAN_B / 32; o <<= 1) {
            int x = __shfl_up_sync(0xffffu, y, o);
            if (lane >= o) y += x;
        }
        ws[lane] = y;
    }
    __syncthreads();
    int off = inc - v + (w > 0 ? ws[w - 1] : 0) + spre;
    if (idx < NN) g_rowptr[idx] = off;
}

// fused: compute t1/t2 from ea, scatter packed 16B CSR record
__global__ void __launch_bounds__(256) k_scatter_t(const float* __restrict__ ea,
                                                   const int* __restrict__ src,
                                                   const int* __restrict__ dst) {
    __shared__ float wv1s[DE], wv2s[DE];
    int tid = threadIdx.x;
    if (tid < DE) { wv1s[tid] = g_wv1[tid]; wv2s[tid] = g_wv2[tid]; }
    __syncthreads();
    int e = blockIdx.x * 256 + tid;           // grid exactly EE/256
    const float4* p = (const float4*)(ea + (size_t)e * DE);
    float t1 = 0.f, t2 = 0.f;
    #pragma unroll
    for (int q = 0; q < 8; q++) {
        float4 v = p[q];
        t1 = fmaf(v.x, wv1s[4*q+0], t1); t1 = fmaf(v.y, wv1s[4*q+1], t1);
        t1 = fmaf(v.z, wv1s[4*q+2], t1); t1 = fmaf(v.w, wv1s[4*q+3], t1);
        t2 = fmaf(v.x, wv2s[4*q+0], t2); t2 = fmaf(v.y, wv2s[4*q+1], t2);
        t2 = fmaf(v.z, wv2s[4*q+2], t2); t2 = fmaf(v.w, wv2s[4*q+3], t2);
    }
    int d = dst[e];
    int pos = g_rowptr[d] + atomicAdd(&g_cnt[d], 1);
    g_csr[pos] = make_float4(__int_as_float(src[e]), t1, t2, 0.f);
}

// ---------------- tiled GEMM (packed-k FFMA2) fused with score epilogue ----------------
template <int DIN, int SRC>
__global__ void __launch_bounds__(256) k_gemm(const float* __restrict__ xin_p,
                                              const float* __restrict__ W,
                                              const float* __restrict__ as,
                                              const float* __restrict__ ad) {
    __shared__ ull  Wp[(DIN / 2) * HH];     // (k-pair, col) packed
    __shared__ float Xs[32 * DIN];
    const float* xin = SRC ? g_x1 : xin_p;
    int tid = threadIdx.x;
    for (int i = tid; i < (DIN / 2) * HH; i += 256) {
        int k2 = i >> 6, c = i & 63;
        Wp[i] = pk2(W[(2 * k2) * HH + c], W[(2 * k2 + 1) * HH + c]);
    }

    const int NT = (NN + 31) / 32;
    int tx = tid & 15, ty = tid >> 4;
    int ra = 2 * ty, rb = 2 * ty + 1;
    float4 as4 = ((const float4*)as)[tx];
    float4 ad4 = ((const float4*)ad)[tx];

    for (int t = blockIdx.x; t < NT; t += gridDim.x) {
        __syncthreads();
        int r0g = t * 32;
        for (int i = tid; i < 32 * DIN / 4; i += 256) {
            int r = i / (DIN / 4), q = i % (DIN / 4);
            float4 vv = (r0g + r < NN) ? ((const float4*)(xin + (size_t)(r0g + r) * DIN))[q]
                                       : make_float4(0.f, 0.f, 0.f, 0.f);
            ((float4*)Xs)[i] = vv;
        }
        __syncthreads();
        const ull* Xa = (const ull*)(Xs + ra * DIN);
        const ull* Xb = (const ull*)(Xs + rb * DIN);
        ull a0 = 0, a1 = 0, a2 = 0, a3 = 0, b0 = 0, b1 = 0, b2 = 0, b3 = 0;
        #pragma unroll 8
        for (int k2 = 0; k2 < DIN / 2; k2++) {
            ull xa = Xa[k2], xb = Xb[k2];
            ulonglong2 wA = ((const ulonglong2*)(Wp + k2 * 64 + 4 * tx))[0];
            ulonglong2 wB = ((const ulonglong2*)(Wp + k2 * 64 + 4 * tx))[1];
            fma2(a0, xa, wA.x); fma2(a1, xa, wA.y); fma2(a2, xa, wB.x); fma2(a3, xa, wB.y);
            fma2(b0, xb, wA.x); fma2(b1, xb, wA.y); fma2(b2, xb, wB.x); fma2(b3, xb, wB.y);
        }
        float2 p0 = upk2(a0), p1 = upk2(a1), p2 = upk2(a2), p3 = upk2(a3);
        float4 aA = make_float4(p0.x + p0.y, p1.x + p1.y, p2.x + p2.y, p3.x + p3.y);
        p0 = upk2(b0); p1 = upk2(b1); p2 = upk2(b2); p3 = upk2(b3);
        float4 aB = make_float4(p0.x + p0.y, p1.x + p1.y, p2.x + p2.y, p3.x + p3.y);

        int gA = r0g + ra, gB = r0g + rb;
        if (gA < NN) ((float4*)(g_h + (size_t)gA * HH))[tx] = aA;
        if (gB < NN) ((float4*)(g_h + (size_t)gB * HH))[tx] = aB;

        float pas = aA.x*as4.x + aA.y*as4.y + aA.z*as4.z + aA.w*as4.w;
        float pad = aA.x*ad4.x + aA.y*ad4.y + aA.z*ad4.z + aA.w*ad4.w;
        float pbs = aB.x*as4.x + aB.y*as4.y + aB.z*as4.z + aB.w*as4.w;
        float pbd = aB.x*ad4.x + aB.y*ad4.y + aB.z*ad4.z + aB.w*ad4.w;
        #pragma unroll
        for (int o = 8; o > 0; o >>= 1) {
            pas += __shfl_xor_sync(0xffffffffu, pas, o);
            pad += __shfl_xor_sync(0xffffffffu, pad, o);
            pbs += __shfl_xor_sync(0xffffffffu, pbs, o);
            pbd += __shfl_xor_sync(0xffffffffu, pbd, o);
        }
        if (tx == 0) {
            if (gA < NN) { g_ssrc[gA] = pas; g_sdst[gA] = pad; }
            if (gB < NN) { g_ssrc[gB] = pbs; g_sdst[gB] = pbd; }
        }
    }
}

// single-pass per-dst softmax + aggregation, packed CSR records
template <int LAYER>
__global__ void __launch_bounds__(256) k_attn(const float* __restrict__ b) {
    int lane = threadIdx.x & 31;
    int n = blockIdx.x * 8 + (threadIdx.x >> 5);   // grid exactly NN/8
    float* xout = LAYER ? g_x2 : g_x1;
    int beg = g_rowptr[n], end = g_rowptr[n + 1];
    float sd = g_sdst[n], ss = g_ssrc[n];

    const ull* h2 = (const ull*)g_h;
    ull acc2 = 0;
    float ssum = 0.f, tsum = 0.f;
    for (int base = beg; base < end; base += 32) {
        int j = base + lane;
        float ev = 0.f; int si = 0;
        if (j < end) {
            float4 rec = g_csr[j];
            si = __float_as_int(rec.x);
            float t = LAYER ? rec.z : rec.y;
            ev = __expf(lrelu(g_ssrc[si] + sd + t));
            tsum += t;
        }
        ssum += ev;
        int cnt = min(32, end - base);
        #pragma unroll 4
        for (int k = 0; k < cnt; k++) {
            int   s = __shfl_sync(0xffffffffu, si, k);
            float w = __shfl_sync(0xffffffffu, ev, k);
            fma2(acc2, pk2(w, w), h2[(size_t)s * 32 + lane]);
        }
    }
    #pragma unroll
    for (int o = 16; o > 0; o >>= 1) {
        ssum += __shfl_xor_sync(0xffffffffu, ssum, o);
        tsum += __shfl_xor_sync(0xffffffffu, tsum, o);
    }

    float deg = (float)(end - beg);
    float tl = tsum / fmaxf(deg, 1.0f);
    float eself = __expf(lrelu(ss + sd + tl));
    float inv = 1.f / (ssum + eself);
    float aself = eself * inv;

    float2 a = upk2(acc2);
    float2 hn = upk2(h2[(size_t)n * 32 + lane]);
    float2 bv = ((const float2*)b)[lane];
    float2 o2;
    o2.x = fmaxf(fmaf(a.x, inv, fmaf(aself, hn.x, bv.x)), 0.f);
    o2.y = fmaxf(fmaf(a.y, inv, fmaf(aself, hn.y, bv.y)), 0.f);
    ((float2*)xout)[(size_t)n * 32 + lane] = o2;
}

// ---------------- classifier ----------------
// u = x2 @ Wc1[0:64], v = x2 @ Wc1[64:128]  (packed-k FFMA2)
__global__ void __launch_bounds__(256) k_gemm_uv(const float* __restrict__ Wc1) {
    __shared__ ull Wu[(HH / 2) * HH];
    __shared__ ull Wv[(HH / 2) * HH];
    __shared__ float Xs[32 * HH];
    int tid = threadIdx.x;
    for (int i = tid; i < (HH / 2) * HH; i += 256) {
        int k2 = i >> 6, c = i & 63;
        Wu[i] = pk2(Wc1[(2 * k2) * HH + c], Wc1[(2 * k2 + 1) * HH + c]);
        Wv[i] = pk2(Wc1[(HH + 2 * k2) * HH + c], Wc1[(HH + 2 * k2 + 1) * HH + c]);
    }
    const int NT = (NN + 31) / 32;
    int tx = tid & 15, ty = tid >> 4;
    int ra = 2 * ty, rb = 2 * ty + 1;
    for (int t = blockIdx.x; t < NT; t += gridDim.x) {
        __syncthreads();
        int r0g = t * 32;
        for (int i = tid; i < 32 * HH / 4; i += 256) {
            int r = i / (HH / 4), q = i % (HH / 4);
            float4 vv = (r0g + r < NN) ? ((const float4*)(g_x2 + (size_t)(r0g + r) * HH))[q]
                                       : make_float4(0.f, 0.f, 0.f, 0.f);
            ((float4*)Xs)[i] = vv;
        }
        __syncthreads();
        const ull* Xa = (const ull*)(Xs + ra * HH);
        const ull* Xb = (const ull*)(Xs + rb * HH);
        ull u0=0,u1=0,u2=0,u3=0, U0=0,U1=0,U2=0,U3=0;
        ull v0=0,v1=0,v2=0,v3=0, V0=0,V1=0,V2=0,V3=0;
        #pragma unroll 8
        for (int k2 = 0; k2 < HH / 2; k2++) {
            ull xa = Xa[k2], xb = Xb[k2];
            ulonglong2 wuA = ((const ulonglong2*)(Wu + k2 * 64 + 4 * tx))[0];
            ulonglong2 wuB = ((const ulonglong2*)(Wu + k2 * 64 + 4 * tx))[1];
            ulonglong2 wvA = ((const ulonglong2*)(Wv + k2 * 64 + 4 * tx))[0];
            ulonglong2 wvB = ((const ulonglong2*)(Wv + k2 * 64 + 4 * tx))[1];
            fma2(u0, xa, wuA.x); fma2(u1, xa, wuA.y); fma2(u2, xa, wuB.x); fma2(u3, xa, wuB.y);
            fma2(U0, xb, wuA.x); fma2(U1, xb, wuA.y); fma2(U2, xb, wuB.x); fma2(U3, xb, wuB.y);
            fma2(v0, xa, wvA.x); fma2(v1, xa, wvA.y); fma2(v2, xa, wvB.x); fma2(v3, xa, wvB.y);
            fma2(V0, xb, wvA.x); fma2(V1, xb, wvA.y); fma2(V2, xb, wvB.x); fma2(V3, xb, wvB.y);
        }
        int gA = r0g + ra, gB = r0g + rb;
        float2 q0, q1, q2, q3;
        if (gA < NN) {
            q0 = upk2(u0); q1 = upk2(u1); q2 = upk2(u2); q3 = upk2(u3);
            ((float4*)(g_u + (size_t)gA * HH))[tx] =
                make_float4(q0.x+q0.y, q1.x+q1.y, q2.x+q2.y, q3.x+q3.y);
            q0 = upk2(v0); q1 = upk2(v1); q2 = upk2(v2); q3 = upk2(v3);
            ((float4*)(g_v + (size_t)gA * HH))[tx] =
                make_float4(q0.x+q0.y, q1.x+q1.y, q2.x+q2.y, q3.x+q3.y);
        }
        if (gB < NN) {
            q0 = upk2(U0); q1 = upk2(U1); q2 = upk2(U2); q3 = upk2(U3);
            ((float4*)(g_u + (size_t)gB * HH))[tx] =
                make_float4(q0.x+q0.y, q1.x+q1.y, q2.x+q2.y, q3.x+q3.y);
            q0 = upk2(V0); q1 = upk2(V1); q2 = upk2(V2); q3 = upk2(V3);
            ((float4*)(g_v + (size_t)gB * HH))[tx] =
                make_float4(q0.x+q0.y, q1.x+q1.y, q2.x+q2.y, q3.x+q3.y);
        }
    }
}

// persistent warp-per-2-edges classifier, f32x2, pipelined gathers
__global__ void __launch_bounds__(256) k_classify(const int* __restrict__ src,
                                                  const int* __restrict__ dst,
                                                  const float* __restrict__ ea,
                                                  const float* __restrict__ Wc1,
                                                  const float* __restrict__ bc1,
                                                  const float* __restrict__ Wc2,
                                                  const float* __restrict__ bc2,
                                                  float* __restrict__ out) {
    __shared__ float eas[16][DE];
    int tid = threadIdx.x, lane = tid & 31, w = tid >> 5;

    ull wcol2[DE];
    #pragma unroll
    for (int k = 0; k < DE; k++)
        wcol2[k] = ((const ull*)(Wc1 + 2 * HH * HH + k * HH))[lane];
    ull  b1v  = ((const ull*)bc1)[lane];
    float2 wc2v = ((const float2*)Wc2)[lane];
    float b2 = bc2[0];

    const ull* u2p = (const ull*)g_u;
    const ull* v2p = (const ull*)g_v;

    for (int eb = blockIdx.x * 16; eb < EE; eb += gridDim.x * 16) {  // EE % 16 == 0
        int e0 = eb + 2 * w, e1 = e0 + 1;
        eas[2*w  ][lane] = ea[(size_t)e0 * DE + lane];
        eas[2*w+1][lane] = ea[(size_t)e1 * DE + lane];
        int s0 = src[e0], d0 = dst[e0], s1 = src[e1], d1 = dst[e1];
        ull Ua = u2p[(size_t)s0 * 32 + lane];
        ull Va = v2p[(size_t)d0 * 32 + lane];
        ull Ub = u2p[(size_t)s1 * 32 + lane];
        ull Vb = v2p[(size_t)d1 * 32 + lane];
        __syncwarp();
        ull acc0 = add2(add2(Ua, Va), b1v);
        ull acc1 = add2(add2(Ub, Vb), b1v);
        #pragma unroll
        for (int k = 0; k < DE; k += 2) {
            float2 ex = *(const float2*)&eas[2*w][k];
            float2 ey = *(const float2*)&eas[2*w+1][k];
            fma2(acc0, pk2(ex.x, ex.x), wcol2[k]);
            fma2(acc0, pk2(ex.y, ex.y), wcol2[k + 1]);
            fma2(acc1, pk2(ey.x, ey.x), wcol2[k]);
            fma2(acc1, pk2(ey.y, ey.y), wcol2[k + 1]);
        }
        float2 a0 = upk2(acc0), a1 = upk2(acc1);
        float r0 = fmaxf(a0.x, 0.f) * wc2v.x + fmaxf(a0.y, 0.f) * wc2v.y;
        float r1 = fmaxf(a1.x, 0.f) * wc2v.x + fmaxf(a1.y, 0.f) * wc2v.y;
        #pragma unroll
        for (int o = 16; o > 0; o >>= 1) {
            r0 += __shfl_xor_sync(0xffffffffu, r0, o);
            r1 += __shfl_xor_sync(0xffffffffu, r1, o);
        }
        if (lane == 0) { out[e0] = r0 + b2; out[e1] = r1 + b2; }
        __syncwarp();
    }
}

// ---------------- host launcher ----------------
extern "C" void kernel_launch(void* const* d_in, const int* in_sizes, int n_in,
                              void* d_out, int out_size) {
    const float* x    = (const float*)d_in[0];
    const int*   ei   = (const int*)  d_in[1];
    const float* ea   = (const float*)d_in[2];
    const float* W1   = (const float*)d_in[3];
    const float* We1  = (const float*)d_in[4];
    const float* as1  = (const float*)d_in[5];
    const float* ad1  = (const float*)d_in[6];
    const float* ae1  = (const float*)d_in[7];
    const float* b1   = (const float*)d_in[8];
    const float* W2   = (const float*)d_in[9];
    const float* We2  = (const float*)d_in[10];
    const float* as2  = (const float*)d_in[11];
    const float* ad2  = (const float*)d_in[12];
    const float* ae2  = (const float*)d_in[13];
    const float* b2   = (const float*)d_in[14];
    const float* Wc1  = (const float*)d_in[15];
    const float* bc1  = (const float*)d_in[16];
    const float* Wc2  = (const float*)d_in[17];
    const float* bc2  = (const float*)d_in[18];
    float*       out  = (float*)d_out;

    const int* src = ei;        // edge_index[0]
    const int* dst = ei + EE;   // edge_index[1]

    const int NB_N = (NN + 255) / 256;
    const int NB_E = EE / 256;          // exact
    const int GEMM_GRID = 592;
    const int CLS_GRID  = 296;

    k_zero_prep<<<NB_N, 256>>>(We1, ae1, We2, ae2);
    k_hist<<<NB_E, 256>>>(dst);
    k_scanA<<<SCAN_G, SCAN_B>>>();
    k_gemm<D0, 0><<<GEMM_GRID, 256>>>(x, W1, as1, ad1);   // independent of CSR; idx 3 for ncu
    k_scanC<<<SCAN_G, SCAN_B>>>();
    k_scatter_t<<<NB_E, 256>>>(ea, src, dst);

    // ---- GAT layer 1 aggregation ----
    k_attn<0><<<NN / 8, 256>>>(b1);

    // ---- GAT layer 2 ----
    k_gemm<HH, 1><<<GEMM_GRID, 256>>>(nullptr, W2, as2, ad2);
    k_attn<1><<<NN / 8, 256>>>(b2);

    // ---- edge classifier ----
    k_gemm_uv<<<GEMM_GRID, 256>>>(Wc1);
    k_classify<<<CLS_GRID, 256>>>(src, dst, ea, Wc1, bc1, Wc2, bc2, out);
}

// round 6
// speedup vs baseline: 3.1272x; 1.1206x over previous
#include <cuda_runtime.h>

#define NN 50000
#define EE 800000
#define HH 64
#define D0 128
#define DE 32
#define NEG 0.2f

typedef unsigned long long ull;

// ---------------- scratch (static device globals; no allocation) ----------------
__device__ __align__(16) float g_h  [NN * HH];
__device__ __align__(16) float g_x1 [NN * HH];
__device__ __align__(16) float g_x2 [NN * HH];
__device__ __align__(16) float g_u  [NN * HH];
__device__ __align__(16) float g_v  [NN * HH];
__device__ float g_ssrc[NN], g_sdst[NN];
__device__ int   g_degi[NN];
__device__ int   g_rowptr[NN + 1];
__device__ int   g_cnt[NN];
__device__ int   g_bsum[128];
__device__ __align__(16) float4 g_csr[EE];   // {src_bits, t1, t2, pad} per edge, CSR by dst
__device__ float g_wv1[DE], g_wv2[DE];

__device__ __forceinline__ float lrelu(float z) { return z >= 0.f ? z : NEG * z; }

// ---- packed f32x2 helpers ----
__device__ __forceinline__ ull pk2(float x, float y) {
    ull r; asm("mov.b64 %0, {%1,%2};" : "=l"(r) : "f"(x), "f"(y)); return r;
}
__device__ __forceinline__ void fma2(ull& d, ull a, ull b) {
    asm("fma.rn.f32x2 %0, %1, %2, %0;" : "+l"(d) : "l"(a), "l"(b));
}
__device__ __forceinline__ ull add2(ull a, ull b) {
    ull r; asm("add.rn.f32x2 %0, %1, %2;" : "=l"(r) : "l"(a), "l"(b)); return r;
}
__device__ __forceinline__ float2 upk2(ull v) {
    float2 f; asm("mov.b64 {%0,%1}, %2;" : "=f"(f.x), "=f"(f.y) : "l"(v)); return f;
}
__device__ __forceinline__ float hsum2(ull v) {
    float2 f = upk2(v); return f.x + f.y;
}

// ---------------- zero counters + prep wv = We @ a_edge ----------------
__global__ void k_zero_prep(const float* __restrict__ We1, const float* __restrict__ ae1,
                            const float* __restrict__ We2, const float* __restrict__ ae2) {
    int i = blockIdx.x * blockDim.x + threadIdx.x;
    if (i < NN) { g_degi[i] = 0; g_cnt[i] = 0; }
    if (i == 0) g_rowptr[NN] = EE;
    if (blockIdx.x == 0 && threadIdx.x >= 32 && threadIdx.x < 64) {
        int k = threadIdx.x - 32;
        float s1 = 0.f, s2 = 0.f;
        #pragma unroll 8
        for (int j = 0; j < HH; j++) {
            s1 = fmaf(We1[k * HH + j], ae1[j], s1);
            s2 = fmaf(We2[k * HH + j], ae2[j], s2);
        }
        g_wv1[k] = s1;
        g_wv2[k] = s2;
    }
}

// degree histogram (dst only)
__global__ void __launch_bounds__(256) k_hist(const int* __restrict__ dst) {
    int e = blockIdx.x * 256 + threadIdx.x;   // grid exactly EE/256
    atomicAdd(&g_degi[dst[e]], 1);
}

// ---------------- parallel scan: degi -> rowptr ----------------
#define SCAN_B 512
#define SCAN_G 98          // 98*512 = 50176 >= NN

__global__ void __launch_bounds__(SCAN_B) k_scanA() {
    __shared__ int ws[SCAN_B / 32];
    int idx = blockIdx.x * SCAN_B + threadIdx.x;
    int v = (idx < NN) ? g_degi[idx] : 0;
    int s = v;
    #pragma unroll
    for (int o = 16; o > 0; o >>= 1) s += __shfl_xor_sync(0xffffffffu, s, o);
    if ((threadIdx.x & 31) == 0) ws[threadIdx.x >> 5] = s;
    __syncthreads();
    if (threadIdx.x < SCAN_B / 32) {
        int t = ws[threadIdx.x];
        #pragma unroll
        for (int o = 8; o > 0; o >>= 1) t += __shfl_xor_sync(0xffffu, t, o);
        if (threadIdx.x == 0) g_bsum[blockIdx.x] = t;
    }
}

__global__ void __launch_bounds__(SCAN_B) k_scanC() {
    __shared__ int wsum[4];
    __shared__ int ws[SCAN_B / 32];
    __shared__ int spre;
    int tid = threadIdx.x, lane = tid & 31, w = tid >> 5;
    if (tid < 128) {
        int pv = (tid < blockIdx.x) ? g_bsum[tid] : 0;
        #pragma unroll
        for (int o = 16; o > 0; o >>= 1) pv += __shfl_xor_sync(0xffffffffu, pv, o);
        if (lane == 0) wsum[w] = pv;
    }
    int idx = blockIdx.x * SCAN_B + tid;
    int v = (idx < NN) ? g_degi[idx] : 0;
    int inc = v;
    #pragma unroll
    for (int o = 1; o < 32; o <<= 1) {
        int x = __shfl_up_sync(0xffffffffu, inc, o);
        if (lane >= o) inc += x;
    }
    if (lane == 31) ws[w] = inc;
    __syncthreads();
    if (tid == 0) spre = wsum[0] + wsum[1] + wsum[2] + wsum[3];
    if (w == 0 && lane < SCAN_B / 32) {
        int y = ws[lane];
        #pragma unroll
        for (int o = 1; o < SCAN_B / 32; o <<= 1) {
            int x = __shfl_up_sync(0xffffu, y, o);
            if (lane >= o) y += x;
        }
        ws[lane] = y;
    }
    __syncthreads();
    int off = inc - v + (w > 0 ? ws[w - 1] : 0) + spre;
    if (idx < NN) g_rowptr[idx] = off;
}

// fused: compute t1/t2 from ea, scatter packed 16B CSR record
__global__ void __launch_bounds__(256) k_scatter_t(const float* __restrict__ ea,
                                                   const int* __restrict__ src,
                                                   const int* __restrict__ dst) {
    __shared__ float wv1s[DE], wv2s[DE];
    int tid = threadIdx.x;
    if (tid < DE) { wv1s[tid] = g_wv1[tid]; wv2s[tid] = g_wv2[tid]; }
    __syncthreads();
    int e = blockIdx.x * 256 + tid;           // grid exactly EE/256
    const float4* p = (const float4*)(ea + (size_t)e * DE);
    float t1 = 0.f, t2 = 0.f;
    #pragma unroll
    for (int q = 0; q < 8; q++) {
        float4 v = p[q];
        t1 = fmaf(v.x, wv1s[4*q+0], t1); t1 = fmaf(v.y, wv1s[4*q+1], t1);
        t1 = fmaf(v.z, wv1s[4*q+2], t1); t1 = fmaf(v.w, wv1s[4*q+3], t1);
        t2 = fmaf(v.x, wv2s[4*q+0], t2); t2 = fmaf(v.y, wv2s[4*q+1], t2);
        t2 = fmaf(v.z, wv2s[4*q+2], t2); t2 = fmaf(v.w, wv2s[4*q+3], t2);
    }
    int d = dst[e];
    int pos = g_rowptr[d] + atomicAdd(&g_cnt[d], 1);
    g_csr[pos] = make_float4(__int_as_float(src[e]), t1, t2, 0.f);
}

// ---------------- GEMM: 64x64 tile, thread = 4 rows x 4 cols, packed-k FFMA2 ----------------
// dynamic smem: Wp[(DIN/2)*64] ull, then Xs[64*DIN] float
template <int DIN, int SRC>
__global__ void __launch_bounds__(256, 2) k_gemm(const float* __restrict__ xin_p,
                                                 const float* __restrict__ W,
                                                 const float* __restrict__ as,
                                                 const float* __restrict__ ad) {
    extern __shared__ char sm[];
    ull*   Wp = (ull*)sm;                              // (DIN/2) * 64
    float* Xs = (float*)(sm + (DIN / 2) * 64 * 8);     // 64 * DIN
    const float* xin = SRC ? g_x1 : xin_p;
    int tid = threadIdx.x;

    for (int i = tid; i < (DIN / 2) * 64; i += 256) {
        int k2 = i >> 6, c = i & 63;
        Wp[i] = pk2(W[(2 * k2) * HH + c], W[(2 * k2 + 1) * HH + c]);
    }
    int r0g = blockIdx.x * 64;                         // grid = ceil(NN/64)
    for (int i = tid; i < 64 * DIN / 4; i += 256) {
        int r = i / (DIN / 4), q = i % (DIN / 4);
        float4 vv = (r0g + r < NN) ? ((const float4*)(xin + (size_t)(r0g + r) * DIN))[q]
                                   : make_float4(0.f, 0.f, 0.f, 0.f);
        ((float4*)Xs)[i] = vv;
    }
    __syncthreads();

    int tx = tid & 15, ty = tid >> 4;                  // cols 4tx..4tx+3, rows 4ty..4ty+3
    const ull* X0 = (const ull*)(Xs + (4 * ty + 0) * DIN);
    const ull* X1 = (const ull*)(Xs + (4 * ty + 1) * DIN);
    const ull* X2 = (const ull*)(Xs + (4 * ty + 2) * DIN);
    const ull* X3 = (const ull*)(Xs + (4 * ty + 3) * DIN);

    ull a00=0,a01=0,a02=0,a03=0, a10=0,a11=0,a12=0,a13=0;
    ull a20=0,a21=0,a22=0,a23=0, a30=0,a31=0,a32=0,a33=0;
    #pragma unroll 8
    for (int k2 = 0; k2 < DIN / 2; k2++) {
        ull x0 = X0[k2], x1 = X1[k2], x2 = X2[k2], x3 = X3[k2];
        ulonglong2 wA = ((const ulonglong2*)(Wp + k2 * 64 + 4 * tx))[0];
        ulonglong2 wB = ((const ulonglong2*)(Wp + k2 * 64 + 4 * tx))[1];
        fma2(a00, x0, wA.x); fma2(a01, x0, wA.y); fma2(a02, x0, wB.x); fma2(a03, x0, wB.y);
        fma2(a10, x1, wA.x); fma2(a11, x1, wA.y); fma2(a12, x1, wB.x); fma2(a13, x1, wB.y);
        fma2(a20, x2, wA.x); fma2(a21, x2, wA.y); fma2(a22, x2, wB.x); fma2(a23, x2, wB.y);
        fma2(a30, x3, wA.x); fma2(a31, x3, wA.y); fma2(a32, x3, wB.x); fma2(a33, x3, wB.y);
    }

    float4 res[4];
    res[0] = make_float4(hsum2(a00), hsum2(a01), hsum2(a02), hsum2(a03));
    res[1] = make_float4(hsum2(a10), hsum2(a11), hsum2(a12), hsum2(a13));
    res[2] = make_float4(hsum2(a20), hsum2(a21), hsum2(a22), hsum2(a23));
    res[3] = make_float4(hsum2(a30), hsum2(a31), hsum2(a32), hsum2(a33));

    float4 as4 = ((const float4*)as)[tx];
    float4 ad4 = ((const float4*)ad)[tx];
    float ps[4], pd[4];
    #pragma unroll
    for (int i = 0; i < 4; i++) {
        int gr = r0g + 4 * ty + i;
        if (gr < NN) ((float4*)(g_h + (size_t)gr * HH))[tx] = res[i];
        ps[i] = res[i].x*as4.x + res[i].y*as4.y + res[i].z*as4.z + res[i].w*as4.w;
        pd[i] = res[i].x*ad4.x + res[i].y*ad4.y + res[i].z*ad4.z + res[i].w*ad4.w;
    }
    #pragma unroll
    for (int o = 8; o > 0; o >>= 1) {
        #pragma unroll
        for (int i = 0; i < 4; i++) {
            ps[i] += __shfl_xor_sync(0xffffffffu, ps[i], o);
            pd[i] += __shfl_xor_sync(0xffffffffu, pd[i], o);
        }
    }
    if (tx == 0) {
        #pragma unroll
        for (int i = 0; i < 4; i++) {
            int gr = r0g + 4 * ty + i;
            if (gr < NN) { g_ssrc[gr] = ps[i]; g_sdst[gr] = pd[i]; }
        }
    }
}

// single-pass per-dst softmax + aggregation, packed CSR records
template <int LAYER>
__global__ void __launch_bounds__(256) k_attn(const float* __restrict__ b) {
    int lane = threadIdx.x & 31;
    int n = blockIdx.x * 8 + (threadIdx.x >> 5);   // grid exactly NN/8
    float* xout = LAYER ? g_x2 : g_x1;
    int beg = g_rowptr[n], end = g_rowptr[n + 1];
    float sd = g_sdst[n], ss = g_ssrc[n];

    const ull* h2 = (const ull*)g_h;
    ull acc2 = 0;
    float ssum = 0.f, tsum = 0.f;
    for (int base = beg; base < end; base += 32) {
        int j = base + lane;
        float ev = 0.f; int si = 0;
        if (j < end) {
            float4 rec = g_csr[j];
            si = __float_as_int(rec.x);
            float t = LAYER ? rec.z : rec.y;
            ev = __expf(lrelu(g_ssrc[si] + sd + t));
            tsum += t;
        }
        ssum += ev;
        int cnt = min(32, end - base);
        #pragma unroll 4
        for (int k = 0; k < cnt; k++) {
            int   s = __shfl_sync(0xffffffffu, si, k);
            float w = __shfl_sync(0xffffffffu, ev, k);
            fma2(acc2, pk2(w, w), h2[(size_t)s * 32 + lane]);
        }
    }
    #pragma unroll
    for (int o = 16; o > 0; o >>= 1) {
        ssum += __shfl_xor_sync(0xffffffffu, ssum, o);
        tsum += __shfl_xor_sync(0xffffffffu, tsum, o);
    }

    float deg = (float)(end - beg);
    float tl = tsum / fmaxf(deg, 1.0f);
    float eself = __expf(lrelu(ss + sd + tl));
    float inv = 1.f / (ssum + eself);
    float aself = eself * inv;

    float2 a = upk2(acc2);
    float2 hn = upk2(h2[(size_t)n * 32 + lane]);
    float2 bv = ((const float2*)b)[lane];
    float2 o2;
    o2.x = fmaxf(fmaf(a.x, inv, fmaf(aself, hn.x, bv.x)), 0.f);
    o2.y = fmaxf(fmaf(a.y, inv, fmaf(aself, hn.y, bv.y)), 0.f);
    ((float2*)xout)[(size_t)n * 32 + lane] = o2;
}

// ---------------- classifier ----------------
// u = x2 @ Wc1[0:64], v = x2 @ Wc1[64:128]  — 64x64 tile, 4 rows x 4 cols per thread
__global__ void __launch_bounds__(256, 2) k_gemm_uv(const float* __restrict__ Wc1) {
    __shared__ ull Wu[(HH / 2) * HH];     // 16 KB
    __shared__ ull Wv[(HH / 2) * HH];     // 16 KB
    __shared__ float Xs[64 * HH];         // 16 KB
    int tid = threadIdx.x;
    for (int i = tid; i < (HH / 2) * HH; i += 256) {
        int k2 = i >> 6, c = i & 63;
        Wu[i] = pk2(Wc1[(2 * k2) * HH + c], Wc1[(2 * k2 + 1) * HH + c]);
        Wv[i] = pk2(Wc1[(HH + 2 * k2) * HH + c], Wc1[(HH + 2 * k2 + 1) * HH + c]);
    }
    int r0g = blockIdx.x * 64;                        // grid = ceil(NN/64)
    for (int i = tid; i < 64 * HH / 4; i += 256) {
        int r = i / (HH / 4), q = i % (HH / 4);
        float4 vv = (r0g + r < NN) ? ((const float4*)(g_x2 + (size_t)(r0g + r) * HH))[q]
                                   : make_float4(0.f, 0.f, 0.f, 0.f);
        ((float4*)Xs)[i] = vv;
    }
    __syncthreads();

    int tx = tid & 15, ty = tid >> 4;
    const ull* X0 = (const ull*)(Xs + (4 * ty + 0) * HH);
    const ull* X1 = (const ull*)(Xs + (4 * ty + 1) * HH);
    const ull* X2 = (const ull*)(Xs + (4 * ty + 2) * HH);
    const ull* X3 = (const ull*)(Xs + (4 * ty + 3) * HH);

    ull u00=0,u01=0,u02=0,u03=0, u10=0,u11=0,u12=0,u13=0;
    ull u20=0,u21=0,u22=0,u23=0, u30=0,u31=0,u32=0,u33=0;
    ull v00=0,v01=0,v02=0,v03=0, v10=0,v11=0,v12=0,v13=0;
    ull v20=0,v21=0,v22=0,v23=0, v30=0,v31=0,v32=0,v33=0;
    #pragma unroll 4
    for (int k2 = 0; k2 < HH / 2; k2++) {
        ull x0 = X0[k2], x1 = X1[k2], x2 = X2[k2], x3 = X3[k2];
        ulonglong2 wuA = ((const ulonglong2*)(Wu + k2 * 64 + 4 * tx))[0];
        ulonglong2 wuB = ((const ulonglong2*)(Wu + k2 * 64 + 4 * tx))[1];
        fma2(u00, x0, wuA.x); fma2(u01, x0, wuA.y); fma2(u02, x0, wuB.x); fma2(u03, x0, wuB.y);
        fma2(u10, x1, wuA.x); fma2(u11, x1, wuA.y); fma2(u12, x1, wuB.x); fma2(u13, x1, wuB.y);
        fma2(u20, x2, wuA.x); fma2(u21, x2, wuA.y); fma2(u22, x2, wuB.x); fma2(u23, x2, wuB.y);
        fma2(u30, x3, wuA.x); fma2(u31, x3, wuA.y); fma2(u32, x3, wuB.x); fma2(u33, x3, wuB.y);
        ulonglong2 wvA = ((const ulonglong2*)(Wv + k2 * 64 + 4 * tx))[0];
        ulonglong2 wvB = ((const ulonglong2*)(Wv + k2 * 64 + 4 * tx))[1];
        fma2(v00, x0, wvA.x); fma2(v01, x0, wvA.y); fma2(v02, x0, wvB.x); fma2(v03, x0, wvB.y);
        fma2(v10, x1, wvA.x); fma2(v11, x1, wvA.y); fma2(v12, x1, wvB.x); fma2(v13, x1, wvB.y);
        fma2(v20, x2, wvA.x); fma2(v21, x2, wvA.y); fma2(v22, x2, wvB.x); fma2(v23, x2, wvB.y);
        fma2(v30, x3, wvA.x); fma2(v31, x3, wvA.y); fma2(v32, x3, wvB.x); fma2(v33, x3, wvB.y);
    }

    int gr0 = r0g + 4 * ty;
    if (gr0 + 0 < NN) {
        ((float4*)(g_u + (size_t)(gr0+0) * HH))[tx] = make_float4(hsum2(u00), hsum2(u01), hsum2(u02), hsum2(u03));
        ((float4*)(g_v + (size_t)(gr0+0) * HH))[tx] = make_float4(hsum2(v00), hsum2(v01), hsum2(v02), hsum2(v03));
    }
    if (gr0 + 1 < NN) {
        ((float4*)(g_u + (size_t)(gr0+1) * HH))[tx] = make_float4(hsum2(u10), hsum2(u11), hsum2(u12), hsum2(u13));
        ((float4*)(g_v + (size_t)(gr0+1) * HH))[tx] = make_float4(hsum2(v10), hsum2(v11), hsum2(v12), hsum2(v13));
    }
    if (gr0 + 2 < NN) {
        ((float4*)(g_u + (size_t)(gr0+2) * HH))[tx] = make_float4(hsum2(u20), hsum2(u21), hsum2(u22), hsum2(u23));
        ((float4*)(g_v + (size_t)(gr0+2) * HH))[tx] = make_float4(hsum2(v20), hsum2(v21), hsum2(v22), hsum2(v23));
    }
    if (gr0 + 3 < NN) {
        ((float4*)(g_u + (size_t)(gr0+3) * HH))[tx] = make_float4(hsum2(u30), hsum2(u31), hsum2(u32), hsum2(u33));
        ((float4*)(g_v + (size_t)(gr0+3) * HH))[tx] = make_float4(hsum2(v30), hsum2(v31), hsum2(v32), hsum2(v33));
    }
}

// persistent warp-per-2-edges classifier, f32x2, pipelined gathers
__global__ void __launch_bounds__(256) k_classify(const int* __restrict__ src,
                                                  const int* __restrict__ dst,
                                                  const float* __restrict__ ea,
                                                  const float* __restrict__ Wc1,
                                                  const float* __restrict__ bc1,
                                                  const float* __restrict__ Wc2,
                                                  const float* __restrict__ bc2,
                                                  float* __restrict__ out) {
    __shared__ float eas[16][DE];
    int tid = threadIdx.x, lane = tid & 31, w = tid >> 5;

    ull wcol2[DE];
    #pragma unroll
    for (int k = 0; k < DE; k++)
        wcol2[k] = ((const ull*)(Wc1 + 2 * HH * HH + k * HH))[lane];
    ull  b1v  = ((const ull*)bc1)[lane];
    float2 wc2v = ((const float2*)Wc2)[lane];
    float b2 = bc2[0];

    const ull* u2p = (const ull*)g_u;
    const ull* v2p = (const ull*)g_v;

    for (int eb = blockIdx.x * 16; eb < EE; eb += gridDim.x * 16) {  // EE % 16 == 0
        int e0 = eb + 2 * w, e1 = e0 + 1;
        eas[2*w  ][lane] = ea[(size_t)e0 * DE + lane];
        eas[2*w+1][lane] = ea[(size_t)e1 * DE + lane];
        int s0 = src[e0], d0 = dst[e0], s1 = src[e1], d1 = dst[e1];
        ull Ua = u2p[(size_t)s0 * 32 + lane];
        ull Va = v2p[(size_t)d0 * 32 + lane];
        ull Ub = u2p[(size_t)s1 * 32 + lane];
        ull Vb = v2p[(size_t)d1 * 32 + lane];
        __syncwarp();
        ull acc0 = add2(add2(Ua, Va), b1v);
        ull acc1 = add2(add2(Ub, Vb), b1v);
        #pragma unroll
        for (int k = 0; k < DE; k += 2) {
            float2 ex = *(const float2*)&eas[2*w][k];
            float2 ey = *(const float2*)&eas[2*w+1][k];
            fma2(acc0, pk2(ex.x, ex.x), wcol2[k]);
            fma2(acc0, pk2(ex.y, ex.y), wcol2[k + 1]);
            fma2(acc1, pk2(ey.x, ey.x), wcol2[k]);
            fma2(acc1, pk2(ey.y, ey.y), wcol2[k + 1]);
        }
        float2 a0 = upk2(acc0), a1 = upk2(acc1);
        float r0 = fmaxf(a0.x, 0.f) * wc2v.x + fmaxf(a0.y, 0.f) * wc2v.y;
        float r1 = fmaxf(a1.x, 0.f) * wc2v.x + fmaxf(a1.y, 0.f) * wc2v.y;
        #pragma unroll
        for (int o = 16; o > 0; o >>= 1) {
            r0 += __shfl_xor_sync(0xffffffffu, r0, o);
            r1 += __shfl_xor_sync(0xffffffffu, r1, o);
        }
        if (lane == 0) { out[e0] = r0 + b2; out[e1] = r1 + b2; }
        __syncwarp();
    }
}

// ---------------- host launcher ----------------
extern "C" void kernel_launch(void* const* d_in, const int* in_sizes, int n_in,
                              void* d_out, int out_size) {
    const float* x    = (const float*)d_in[0];
    const int*   ei   = (const int*)  d_in[1];
    const float* ea   = (const float*)d_in[2];
    const float* W1   = (const float*)d_in[3];
    const float* We1  = (const float*)d_in[4];
    const float* as1  = (const float*)d_in[5];
    const float* ad1  = (const float*)d_in[6];
    const float* ae1  = (const float*)d_in[7];
    const float* b1   = (const float*)d_in[8];
    const float* W2   = (const float*)d_in[9];
    const float* We2  = (const float*)d_in[10];
    const float* as2  = (const float*)d_in[11];
    const float* ad2  = (const float*)d_in[12];
    const float* ae2  = (const float*)d_in[13];
    const float* b2   = (const float*)d_in[14];
    const float* Wc1  = (const float*)d_in[15];
    const float* bc1  = (const float*)d_in[16];
    const float* Wc2  = (const float*)d_in[17];
    const float* bc2  = (const float*)d_in[18];
    float*       out  = (float*)d_out;

    const int* src = ei;        // edge_index[0]
    const int* dst = ei + EE;   // edge_index[1]

    const int NB_N = (NN + 255) / 256;
    const int NB_E = EE / 256;               // exact
    const int NT64 = (NN + 63) / 64;         // 782
    const int CLS_GRID = 296;

    // smem: DIN=128 -> 32KB W + 32KB X = 64KB (needs opt-in); DIN=64 -> 32KB
    const int SMEM_G1 = (D0 / 2) * 64 * 8 + 64 * D0 * 4;   // 65536
    const int SMEM_G2 = (HH / 2) * 64 * 8 + 64 * HH * 4;   // 32768
    cudaFuncSetAttribute(k_gemm<D0, 0>, cudaFuncAttributeMaxDynamicSharedMemorySize, SMEM_G1);

    k_zero_prep<<<NB_N, 256>>>(We1, ae1, We2, ae2);
    k_hist<<<NB_E, 256>>>(dst);
    k_scanA<<<SCAN_G, SCAN_B>>>();
    k_gemm<D0, 0><<<NT64, 256, SMEM_G1>>>(x, W1, as1, ad1);   // independent of CSR build
    k_scanC<<<SCAN_G, SCAN_B>>>();
    k_scatter_t<<<NB_E, 256>>>(ea, src, dst);

    // ---- GAT layer 1 aggregation ----
    k_attn<0><<<NN / 8, 256>>>(b1);

    // ---- GAT layer 2 ----
    k_gemm<HH, 1><<<NT64, 256, SMEM_G2>>>(nullptr, W2, as2, ad2);
    k_attn<1><<<NN / 8, 256>>>(b2);

    // ---- edge classifier ----
    k_gemm_uv<<<NT64, 256>>>(Wc1);
    k_classify<<<CLS_GRID, 256>>>(src, dst, ea, Wc1, bc1, Wc2, bc2, out);
}